// round 1
// baseline (speedup 1.0000x reference)
#include <cuda_runtime.h>
#include <math.h>

#define B_ 4
#define T_ 4096
#define D_ 1024
#define H_ 8
#define DH_ 128
#define NTOK (B_ * T_)          // 16384
#define NEGV (-1000000.0f)

// ---------------- scratch (device globals; no allocations allowed) ----------
__device__ float g_xn[(size_t)NTOK * D_];          // 64 MB  LayerNorm output
__device__ float g_q [(size_t)NTOK * D_];          // 64 MB  q (raw, then softmaxed in place)
__device__ float g_k [(size_t)NTOK * D_];          // 64 MB  k (pre time-softmax, mask added)
__device__ float g_v [(size_t)NTOK * D_];          // 64 MB  v (masked)
__device__ float g_cmax_part[B_ * D_ * 16];        // partial col max [col][chunk]
__device__ float g_cmax[B_ * D_];                  // col max per (b, d)
__device__ float g_attp[(size_t)8 * B_ * H_ * DH_ * DH_]; // [split][bh][d][l]
__device__ float g_Sp[(size_t)8 * B_ * D_];        // [split][bh*128+d]
__device__ float g_att[(size_t)B_ * H_ * DH_ * DH_];      // normalized att

// ---------------- LayerNorm: one block per token ----------------------------
__global__ void __launch_bounds__(256) ln_kernel(const float* __restrict__ x,
                                                 const float* __restrict__ gamma,
                                                 const float* __restrict__ beta) {
    __shared__ float red[16];
    const int row = blockIdx.x;
    const int tid = threadIdx.x;
    const float4 v = ((const float4*)(x + (size_t)row * D_))[tid];
    float s  = v.x + v.y + v.z + v.w;
    float ss = v.x * v.x + v.y * v.y + v.z * v.z + v.w * v.w;
#pragma unroll
    for (int o = 16; o > 0; o >>= 1) {
        s  += __shfl_xor_sync(0xffffffffu, s, o);
        ss += __shfl_xor_sync(0xffffffffu, ss, o);
    }
    const int warp = tid >> 5, lane = tid & 31;
    if (lane == 0) { red[warp] = s; red[warp + 8] = ss; }
    __syncthreads();
    if (tid < 32) {
        float a = (tid < 8) ? red[tid] : 0.f;
        float b = (tid < 8) ? red[tid + 8] : 0.f;
#pragma unroll
        for (int o = 4; o > 0; o >>= 1) {
            a += __shfl_xor_sync(0xffffffffu, a, o);
            b += __shfl_xor_sync(0xffffffffu, b, o);
        }
        if (tid == 0) { red[0] = a; red[1] = b; }
    }
    __syncthreads();
    const float mu   = red[0] * (1.0f / D_);
    const float var  = red[1] * (1.0f / D_) - mu * mu;
    const float rstd = rsqrtf(var + 1e-5f);
    const float4 g  = ((const float4*)gamma)[tid];
    const float4 bb = ((const float4*)beta)[tid];
    float4 o;
    o.x = (v.x - mu) * rstd * g.x + bb.x;
    o.y = (v.y - mu) * rstd * g.y + bb.y;
    o.z = (v.z - mu) * rstd * g.z + bb.z;
    o.w = (v.w - mu) * rstd * g.w + bb.w;
    ((float4*)(g_xn + (size_t)row * D_))[tid] = o;
}

// ---------------- QKV GEMM: C = xn @ W + bias (+mask epilogue) ---------------
// Tile 128x128x16, 256 threads, 8x8 microtile with split-fragment float4s.
// mode 0: q = acc+bias ; mode 1: k = acc+bias+(1-m)*NEG ; mode 2: v = (acc+bias)*m
__global__ void __launch_bounds__(256) qkv_gemm(const float* __restrict__ W,
                                                const float* __restrict__ bias,
                                                const float* __restrict__ mask,
                                                int mode) {
    __shared__ float As[16][128];   // As[k][m] (transposed)
    __shared__ float Bs[16][128];   // Bs[k][n]
    float* __restrict__ C = (mode == 0) ? g_q : (mode == 1) ? g_k : g_v;
    const int tid = threadIdx.x;
    const int bm = blockIdx.y, bn = blockIdx.x;
    const int tx = tid & 15, ty = tid >> 4;
    const size_t arow0 = (size_t)bm * 128;

    float acc[8][8];
#pragma unroll
    for (int i = 0; i < 8; i++)
#pragma unroll
        for (int j = 0; j < 8; j++) acc[i][j] = 0.f;

    for (int k0 = 0; k0 < 1024; k0 += 16) {
#pragma unroll
        for (int s = 0; s < 2; s++) {
            const int idx = tid + s * 256;             // 0..511
            const int ar = idx >> 2, ac = (idx & 3) * 4;
            const float4 a = *(const float4*)(g_xn + (arow0 + ar) * 1024 + k0 + ac);
            As[ac + 0][ar] = a.x; As[ac + 1][ar] = a.y;
            As[ac + 2][ar] = a.z; As[ac + 3][ar] = a.w;
            const int br = idx >> 5, bc = (idx & 31) * 4;
            *(float4*)&Bs[br][bc] =
                *(const float4*)(W + (size_t)(k0 + br) * 1024 + bn * 128 + bc);
        }
        __syncthreads();
#pragma unroll
        for (int kk = 0; kk < 16; kk++) {
            float a[8], b[8];
            *(float4*)&a[0] = *(float4*)&As[kk][ty * 4];
            *(float4*)&a[4] = *(float4*)&As[kk][64 + ty * 4];
            *(float4*)&b[0] = *(float4*)&Bs[kk][tx * 4];
            *(float4*)&b[4] = *(float4*)&Bs[kk][64 + tx * 4];
#pragma unroll
            for (int i = 0; i < 8; i++)
#pragma unroll
                for (int j = 0; j < 8; j++) acc[i][j] += a[i] * b[j];
        }
        __syncthreads();
    }
#pragma unroll
    for (int i = 0; i < 8; i++) {
        const int r = (i < 4) ? (ty * 4 + i) : (64 + ty * 4 + i - 4);
        const size_t row = arow0 + r;
        const float mk = mask[row];
        const float madd = (mode == 1) ? (1.0f - mk) * NEGV : 0.f;
        const float mmul = (mode == 2) ? mk : 1.f;
#pragma unroll
        for (int jj = 0; jj < 2; jj++) {
            const int cl = (jj == 0) ? (tx * 4) : (64 + tx * 4);
            const int c0 = bn * 128 + cl;
            float4 o;
            o.x = (acc[i][jj * 4 + 0] + bias[c0 + 0] + madd) * mmul;
            o.y = (acc[i][jj * 4 + 1] + bias[c0 + 1] + madd) * mmul;
            o.z = (acc[i][jj * 4 + 2] + bias[c0 + 2] + madd) * mmul;
            o.w = (acc[i][jj * 4 + 3] + bias[c0 + 3] + madd) * mmul;
            *(float4*)(C + row * 1024 + c0) = o;
        }
    }
}

// ---------------- q softmax over head-feature dim (128), one warp per row ---
__global__ void __launch_bounds__(256) qsoftmax_kernel() {
    const int idx = blockIdx.x * 8 + (threadIdx.x >> 5);  // token*8 + head
    const int lane = threadIdx.x & 31;
    float4* p = (float4*)(g_q + (size_t)idx * 128);
    float4 v = p[lane];
    float m = fmaxf(fmaxf(v.x, v.y), fmaxf(v.z, v.w));
#pragma unroll
    for (int o = 16; o > 0; o >>= 1) m = fmaxf(m, __shfl_xor_sync(0xffffffffu, m, o));
    v.x = __expf(v.x - m); v.y = __expf(v.y - m);
    v.z = __expf(v.z - m); v.w = __expf(v.w - m);
    float s = v.x + v.y + v.z + v.w;
#pragma unroll
    for (int o = 16; o > 0; o >>= 1) s += __shfl_xor_sync(0xffffffffu, s, o);
    const float inv = 1.0f / s;
    v.x *= inv; v.y *= inv; v.z *= inv; v.w *= inv;
    p[lane] = v;
}

// ---------------- k column max over time (2-pass) ----------------------------
__global__ void __launch_bounds__(256) kmax_part_kernel() {
    const int col = blockIdx.x * 256 + threadIdx.x;       // 0..4095 (b*1024+d)
    const int b = col >> 10, d = col & 1023;
    const float* base = g_k + ((size_t)b * T_) * D_ + d;
    const int t0 = blockIdx.y * 256;
    float m = -3.4e38f;
#pragma unroll 8
    for (int t = 0; t < 256; t++) m = fmaxf(m, base[(size_t)(t0 + t) * D_]);
    g_cmax_part[col * 16 + blockIdx.y] = m;
}

__global__ void __launch_bounds__(256) kmax_final_kernel() {
    const int col = blockIdx.x * 256 + threadIdx.x;
    float m = g_cmax_part[col * 16];
#pragma unroll
    for (int p = 1; p < 16; p++) m = fmaxf(m, g_cmax_part[col * 16 + p]);
    g_cmax[col] = m;
}

// ---------------- att partial: U[d][l] = sum_t exp(k-M)*v ; S[d] = sum exp ---
// grid (bh=32, split=8); each block: 128x128 output over 512 timesteps.
__global__ void __launch_bounds__(256) att_part_kernel() {
    __shared__ float Es[32][128];
    __shared__ float Vs[32][128];
    __shared__ float Ms[128];
    const int bh = blockIdx.x, sp = blockIdx.y;
    const int b = bh >> 3, h = bh & 7;
    const int tid = threadIdx.x;
    const int tx = tid & 15, ty = tid >> 4;
    if (tid < 128) Ms[tid] = g_cmax[b * 1024 + h * 128 + tid];
    __syncthreads();

    float acc[8][8];
#pragma unroll
    for (int i = 0; i < 8; i++)
#pragma unroll
        for (int j = 0; j < 8; j++) acc[i][j] = 0.f;
    float sacc[8];
#pragma unroll
    for (int i = 0; i < 8; i++) sacc[i] = 0.f;

    const size_t base = ((size_t)b * T_) * D_ + h * 128;
    for (int t0 = sp * 512; t0 < sp * 512 + 512; t0 += 32) {
#pragma unroll
        for (int s = 0; s < 4; s++) {
            const int idx = tid + s * 256;              // 0..1023
            const int tr = idx >> 5, dc = (idx & 31) * 4;
            const size_t off = base + (size_t)(t0 + tr) * D_ + dc;
            const float4 kv = *(const float4*)(g_k + off);
            float4 e;
            e.x = __expf(kv.x - Ms[dc + 0]);
            e.y = __expf(kv.y - Ms[dc + 1]);
            e.z = __expf(kv.z - Ms[dc + 2]);
            e.w = __expf(kv.w - Ms[dc + 3]);
            *(float4*)&Es[tr][dc] = e;
            *(float4*)&Vs[tr][dc] = *(const float4*)(g_v + off);
        }
        __syncthreads();
#pragma unroll
        for (int kk = 0; kk < 32; kk++) {
            float a[8], bb[8];
            *(float4*)&a[0]  = *(float4*)&Es[kk][ty * 4];
            *(float4*)&a[4]  = *(float4*)&Es[kk][64 + ty * 4];
            *(float4*)&bb[0] = *(float4*)&Vs[kk][tx * 4];
            *(float4*)&bb[4] = *(float4*)&Vs[kk][64 + tx * 4];
#pragma unroll
            for (int i = 0; i < 8; i++)
#pragma unroll
                for (int j = 0; j < 8; j++) acc[i][j] += a[i] * bb[j];
            if (tx == 0) {
#pragma unroll
                for (int i = 0; i < 8; i++) sacc[i] += a[i];
            }
        }
        __syncthreads();
    }
    const size_t obase = ((size_t)sp * 32 + bh) * 16384;
#pragma unroll
    for (int i = 0; i < 8; i++) {
        const int r = (i < 4) ? (ty * 4 + i) : (64 + ty * 4 + i - 4);
#pragma unroll
        for (int jj = 0; jj < 2; jj++) {
            const int c = (jj == 0) ? (tx * 4) : (64 + tx * 4);
            float4 o;
            o.x = acc[i][jj * 4 + 0]; o.y = acc[i][jj * 4 + 1];
            o.z = acc[i][jj * 4 + 2]; o.w = acc[i][jj * 4 + 3];
            *(float4*)(g_attp + obase + (size_t)r * 128 + c) = o;
        }
        if (tx == 0) g_Sp[(size_t)sp * 4096 + bh * 128 + r] = sacc[i];
    }
}

// ---------------- att reduce: sum partials, normalize by S -------------------
__global__ void __launch_bounds__(256) att_reduce_kernel() {
    __shared__ float Ss[128];
    const int bh = blockIdx.x;
    const int tid = threadIdx.x;
    if (tid < 128) {
        float s = 0.f;
#pragma unroll
        for (int p = 0; p < 8; p++) s += g_Sp[(size_t)p * 4096 + bh * 128 + tid];
        Ss[tid] = 1.0f / s;
    }
    __syncthreads();
    for (int e = tid; e < 16384; e += 256) {
        const int d = e >> 7;
        float s = 0.f;
#pragma unroll
        for (int p = 0; p < 8; p++) s += g_attp[((size_t)p * 32 + bh) * 16384 + e];
        g_att[(size_t)bh * 16384 + e] = s * Ss[d];
    }
}

// ---------------- y = q_sm @ att, out = x + y -------------------------------
// grid (token tile=32, bh=32); tile 128x128, K=128 in steps of 16.
__global__ void __launch_bounds__(256) ygemm_kernel(const float* __restrict__ x,
                                                    float* __restrict__ out) {
    __shared__ float As[16][128];   // As[d][t]
    __shared__ float Bs[16][128];   // att[d][l]
    const int bh = blockIdx.y, mt = blockIdx.x;
    const int b = bh >> 3, h = bh & 7;
    const int tid = threadIdx.x;
    const int tx = tid & 15, ty = tid >> 4;
    const size_t qbase = ((size_t)b * T_ + mt * 128) * D_ + h * 128;
    const size_t attbase = (size_t)bh * 16384;

    float acc[8][8];
#pragma unroll
    for (int i = 0; i < 8; i++)
#pragma unroll
        for (int j = 0; j < 8; j++) acc[i][j] = 0.f;

    for (int k0 = 0; k0 < 128; k0 += 16) {
#pragma unroll
        for (int s = 0; s < 2; s++) {
            const int idx = tid + s * 256;
            const int ar = idx >> 2, ac = (idx & 3) * 4;
            const float4 a = *(const float4*)(g_q + qbase + (size_t)ar * D_ + k0 + ac);
            As[ac + 0][ar] = a.x; As[ac + 1][ar] = a.y;
            As[ac + 2][ar] = a.z; As[ac + 3][ar] = a.w;
            const int br = idx >> 5, bc = (idx & 31) * 4;
            *(float4*)&Bs[br][bc] =
                *(const float4*)(g_att + attbase + (size_t)(k0 + br) * 128 + bc);
        }
        __syncthreads();
#pragma unroll
        for (int kk = 0; kk < 16; kk++) {
            float a[8], bb[8];
            *(float4*)&a[0]  = *(float4*)&As[kk][ty * 4];
            *(float4*)&a[4]  = *(float4*)&As[kk][64 + ty * 4];
            *(float4*)&bb[0] = *(float4*)&Bs[kk][tx * 4];
            *(float4*)&bb[4] = *(float4*)&Bs[kk][64 + tx * 4];
#pragma unroll
            for (int i = 0; i < 8; i++)
#pragma unroll
                for (int j = 0; j < 8; j++) acc[i][j] += a[i] * bb[j];
        }
        __syncthreads();
    }
#pragma unroll
    for (int i = 0; i < 8; i++) {
        const int r = (i < 4) ? (ty * 4 + i) : (64 + ty * 4 + i - 4);
        const size_t row = (size_t)b * T_ + mt * 128 + r;
#pragma unroll
        for (int jj = 0; jj < 2; jj++) {
            const int c = (jj == 0) ? (tx * 4) : (64 + tx * 4);
            const size_t o = row * D_ + h * 128 + c;
            const float4 xres = *(const float4*)(x + o);
            float4 ov;
            ov.x = acc[i][jj * 4 + 0] + xres.x;
            ov.y = acc[i][jj * 4 + 1] + xres.y;
            ov.z = acc[i][jj * 4 + 2] + xres.z;
            ov.w = acc[i][jj * 4 + 3] + xres.w;
            *(float4*)(out + o) = ov;
        }
    }
}

// ---------------- launcher ---------------------------------------------------
extern "C" void kernel_launch(void* const* d_in, const int* in_sizes, int n_in,
                              void* d_out, int out_size) {
    const float* x     = (const float*)d_in[0];
    const float* mask  = (const float*)d_in[1];
    const float* Wq    = (const float*)d_in[2];
    const float* bq    = (const float*)d_in[3];
    const float* Wk    = (const float*)d_in[4];
    const float* bk    = (const float*)d_in[5];
    const float* Wv    = (const float*)d_in[6];
    const float* bv    = (const float*)d_in[7];
    const float* gamma = (const float*)d_in[8];
    const float* beta  = (const float*)d_in[9];
    float* out = (float*)d_out;

    ln_kernel<<<NTOK, 256>>>(x, gamma, beta);

    dim3 gg(8, 128);   // (n tiles, m tiles)
    qkv_gemm<<<gg, 256>>>(Wq, bq, mask, 0);
    qkv_gemm<<<gg, 256>>>(Wk, bk, mask, 1);
    qkv_gemm<<<gg, 256>>>(Wv, bv, mask, 2);

    qsoftmax_kernel<<<NTOK * H_ / 8, 256>>>();

    kmax_part_kernel<<<dim3(16, 16), 256>>>();
    kmax_final_kernel<<<16, 256>>>();

    att_part_kernel<<<dim3(32, 8), 256>>>();
    att_reduce_kernel<<<32, 256>>>();

    ygemm_kernel<<<dim3(32, 32), 256>>>(x, out);
}

// round 3
// speedup vs baseline: 2.3025x; 2.3025x over previous
#include <cuda_runtime.h>
#include <cuda_bf16.h>
#include <stdint.h>
#include <math.h>

#define B_ 4
#define T_ 4096
#define D_ 1024
#define H_ 8
#define DH_ 128
#define NTOK (B_ * T_)          // 16384
#define NEGV (-1000000.0f)

// ---------------- scratch (device globals; no allocations allowed) ----------
__device__ __nv_bfloat16 g_xnh[(size_t)NTOK * D_];     // 32 MB  xn hi
__device__ __nv_bfloat16 g_xnl[(size_t)NTOK * D_];     // 32 MB  xn lo
__device__ __nv_bfloat16 g_wth[(size_t)3 * D_ * D_];   // 6 MB   W^T hi (q,k,v)
__device__ __nv_bfloat16 g_wtl[(size_t)3 * D_ * D_];   // 6 MB   W^T lo
__device__ float g_q [(size_t)NTOK * D_];
__device__ float g_k [(size_t)NTOK * D_];
__device__ float g_v [(size_t)NTOK * D_];
__device__ float g_cmax_part[B_ * D_ * 16];
__device__ float g_cmax[B_ * D_];
__device__ float g_attp[(size_t)8 * B_ * H_ * DH_ * DH_];
__device__ float g_Sp[(size_t)8 * B_ * D_];
__device__ float g_att[(size_t)B_ * H_ * DH_ * DH_];

// ======================= PTX helpers (sm_103 baseline ISA only) ==============
__device__ __forceinline__ uint32_t smem_u32(const void* p) {
    uint32_t a;
    asm("{ .reg .u64 t; cvta.to.shared.u64 t, %1; cvt.u32.u64 %0, t; }"
        : "=r"(a) : "l"(p));
    return a;
}
__device__ __forceinline__ void cp16(uint32_t d, const void* g) {
    asm volatile("cp.async.cg.shared.global [%0], [%1], 16;" :: "r"(d), "l"(g));
}
#define CP_COMMIT()  asm volatile("cp.async.commit_group;")
#define CP_WAIT(n)   asm volatile("cp.async.wait_group %0;" :: "n"(n) : "memory")
#define SW128(o) ((uint32_t)(o) ^ ((((uint32_t)(o)) >> 3) & 0x70))

__device__ __forceinline__ void ldsm_x4(uint32_t& r0, uint32_t& r1,
                                        uint32_t& r2, uint32_t& r3, uint32_t a) {
    asm volatile("ldmatrix.sync.aligned.m8n8.x4.shared.b16 {%0,%1,%2,%3}, [%4];"
                 : "=r"(r0), "=r"(r1), "=r"(r2), "=r"(r3) : "r"(a));
}
__device__ __forceinline__ void mma16816(float* d, const uint32_t* a,
                                         const uint32_t* b) {
    asm volatile("mma.sync.aligned.m16n8k16.row.col.f32.bf16.bf16.f32 "
                 "{%0,%1,%2,%3}, {%4,%5,%6,%7}, {%8,%9}, {%0,%1,%2,%3};"
                 : "+f"(d[0]), "+f"(d[1]), "+f"(d[2]), "+f"(d[3])
                 : "r"(a[0]), "r"(a[1]), "r"(a[2]), "r"(a[3]),
                   "r"(b[0]), "r"(b[1]));
}

// ---------------- LayerNorm: one block per token; emits bf16 hi/lo ----------
__global__ void __launch_bounds__(256) ln_kernel(const float* __restrict__ x,
                                                 const float* __restrict__ gamma,
                                                 const float* __restrict__ beta) {
    __shared__ float red[16];
    const int row = blockIdx.x;
    const int tid = threadIdx.x;
    const float4 v = ((const float4*)(x + (size_t)row * D_))[tid];
    float s  = v.x + v.y + v.z + v.w;
    float ss = v.x * v.x + v.y * v.y + v.z * v.z + v.w * v.w;
#pragma unroll
    for (int o = 16; o > 0; o >>= 1) {
        s  += __shfl_xor_sync(0xffffffffu, s, o);
        ss += __shfl_xor_sync(0xffffffffu, ss, o);
    }
    const int warp = tid >> 5, lane = tid & 31;
    if (lane == 0) { red[warp] = s; red[warp + 8] = ss; }
    __syncthreads();
    if (tid < 32) {
        float a = (tid < 8) ? red[tid] : 0.f;
        float b = (tid < 8) ? red[tid + 8] : 0.f;
#pragma unroll
        for (int o = 4; o > 0; o >>= 1) {
            a += __shfl_xor_sync(0xffffffffu, a, o);
            b += __shfl_xor_sync(0xffffffffu, b, o);
        }
        if (tid == 0) { red[0] = a; red[1] = b; }
    }
    __syncthreads();
    const float mu   = red[0] * (1.0f / D_);
    const float var  = red[1] * (1.0f / D_) - mu * mu;
    const float rstd = rsqrtf(var + 1e-5f);
    const float4 g  = ((const float4*)gamma)[tid];
    const float4 bb = ((const float4*)beta)[tid];
    float o0 = (v.x - mu) * rstd * g.x + bb.x;
    float o1 = (v.y - mu) * rstd * g.y + bb.y;
    float o2 = (v.z - mu) * rstd * g.z + bb.z;
    float o3 = (v.w - mu) * rstd * g.w + bb.w;
    const size_t off = (size_t)row * D_ + tid * 4;
    __nv_bfloat162 h01 = __floats2bfloat162_rn(o0, o1);
    __nv_bfloat162 h23 = __floats2bfloat162_rn(o2, o3);
    *(__nv_bfloat162*)(g_xnh + off)     = h01;
    *(__nv_bfloat162*)(g_xnh + off + 2) = h23;
    __nv_bfloat162 l01 = __floats2bfloat162_rn(o0 - __bfloat162float(h01.x),
                                               o1 - __bfloat162float(h01.y));
    __nv_bfloat162 l23 = __floats2bfloat162_rn(o2 - __bfloat162float(h23.x),
                                               o3 - __bfloat162float(h23.y));
    *(__nv_bfloat162*)(g_xnl + off)     = l01;
    *(__nv_bfloat162*)(g_xnl + off + 2) = l23;
}

// ---------------- W transpose + hi/lo split: Wt[n][k] = W[k][n] --------------
__global__ void __launch_bounds__(256) wsplit_kernel(const float* __restrict__ Wq,
                                                     const float* __restrict__ Wk,
                                                     const float* __restrict__ Wv) {
    __shared__ float t[32][33];
    const float* W = (blockIdx.z == 0) ? Wq : (blockIdx.z == 1) ? Wk : Wv;
    __nv_bfloat16* oh = g_wth + ((size_t)blockIdx.z << 20);
    __nv_bfloat16* ol = g_wtl + ((size_t)blockIdx.z << 20);
    const int tid = threadIdx.x;
    const int tx = tid & 31, ty = tid >> 5;
    const int bn = blockIdx.x * 32, bk = blockIdx.y * 32;
#pragma unroll
    for (int r = ty; r < 32; r += 8)
        t[r][tx] = W[(size_t)(bk + r) * 1024 + bn + tx];
    __syncthreads();
#pragma unroll
    for (int r = ty; r < 32; r += 8) {
        const float v = t[tx][r];                 // = W[bk+tx][bn+r]
        const __nv_bfloat16 h = __float2bfloat16_rn(v);
        const __nv_bfloat16 l = __float2bfloat16_rn(v - __bfloat162float(h));
        const size_t o = (size_t)(bn + r) * 1024 + bk + tx;
        oh[o] = h; ol[o] = l;
    }
}

// ---------------- QKV GEMM via mma.sync bf16, 3-term split -------------------
// Tile 128(M) x 128(N), BK=64, 2-stage cp.async double buffer, 256 threads.
// 8 warps: warp (wm in 0..1, wn in 0..3) owns 64x32.
// grid (8 n-tiles, 128 m-tiles, 3 modes). mode 0:q 1:k 2:v.
#define OFF_AH 0
#define OFF_AL 16384
#define OFF_BH 32768
#define OFF_BL 49152
#define STG    65536
#define QK_SMEM (2 * STG + 1024)

__global__ void __launch_bounds__(256, 1)
qkv_mma(const float* __restrict__ bq, const float* __restrict__ bk_,
        const float* __restrict__ bv, const float* __restrict__ mask) {
    extern __shared__ char dsm[];
    const uint32_t base = (smem_u32(dsm) + 1023) & ~1023u;
    const int tid = threadIdx.x, lane = tid & 31, wid = tid >> 5;
    const int wm = wid & 1, wn = wid >> 1;
    const int mode = blockIdx.z;
    const int n0 = blockIdx.x * 128;
    const size_t m0 = (size_t)blockIdx.y * 128;

    const __nv_bfloat16* Ah = g_xnh;
    const __nv_bfloat16* Al = g_xnl;
    const __nv_bfloat16* Bh = g_wth + ((size_t)mode << 20);
    const __nv_bfloat16* Bl = g_wtl + ((size_t)mode << 20);

    float acc[4][4][4];
#pragma unroll
    for (int i = 0; i < 4; i++)
#pragma unroll
        for (int j = 0; j < 4; j++)
#pragma unroll
            for (int q = 0; q < 4; q++) acc[i][j][q] = 0.f;

    // ---- stage loader: 128 rows x 64 k for A(hi,lo) and B(hi,lo) ----
    auto issue = [&](int i) {
        const int k0 = i * 64;
        const uint32_t sb = base + (i & 1) * STG;
#pragma unroll
        for (int p = 0; p < 4; p++) {
            const int idx = p * 256 + tid;             // 0..1023
            const int r = idx >> 3;
            const int kc = (idx & 7);
            const uint32_t sw = SW128(r * 128 + kc * 16);
            const size_t ga = (m0 + r) * 1024 + k0 + kc * 8;
            cp16(sb + OFF_AH + sw, Ah + ga);
            cp16(sb + OFF_AL + sw, Al + ga);
            const size_t gb = (size_t)(n0 + r) * 1024 + k0 + kc * 8;
            cp16(sb + OFF_BH + sw, Bh + gb);
            cp16(sb + OFF_BL + sw, Bl + gb);
        }
        CP_COMMIT();
    };

    issue(0);
    for (int i = 0; i < 16; i++) {
        if (i + 1 < 16) { issue(i + 1); CP_WAIT(1); }
        else            { CP_WAIT(0); }
        __syncthreads();
        const uint32_t sb = base + (i & 1) * STG;

        // precomputed per-lane ldmatrix address components
        const int arow = wm * 64 + (lane & 15);        // + mi*16
        const int acolb = (lane >> 4) * 16;            // + kk0*2
        const int brow = wn * 32 + (lane & 7) + ((lane & 16) ? 8 : 0); // + nib*16
        const int bcolb = (lane & 8) ? 16 : 0;         // + kk0*2

#pragma unroll
        for (int ks = 0; ks < 4; ks++) {
            const int kb = ks * 32;                    // byte offset of k16 chunk
            uint32_t ah[4][4], al[4][4], bh[2][4], bl[2][4];
#pragma unroll
            for (int mi = 0; mi < 4; mi++) {
                const uint32_t ao = SW128((arow + mi * 16) * 128 + kb + acolb);
                ldsm_x4(ah[mi][0], ah[mi][1], ah[mi][2], ah[mi][3],
                        sb + OFF_AH + ao);
                ldsm_x4(al[mi][0], al[mi][1], al[mi][2], al[mi][3],
                        sb + OFF_AL + ao);
            }
#pragma unroll
            for (int nb = 0; nb < 2; nb++) {
                const uint32_t bo = SW128((brow + nb * 16) * 128 + kb + bcolb);
                ldsm_x4(bh[nb][0], bh[nb][1], bh[nb][2], bh[nb][3],
                        sb + OFF_BH + bo);
                ldsm_x4(bl[nb][0], bl[nb][1], bl[nb][2], bl[nb][3],
                        sb + OFF_BL + bo);
            }
#pragma unroll
            for (int mi = 0; mi < 4; mi++)
#pragma unroll
                for (int ni = 0; ni < 4; ni++) {
                    const uint32_t* bhp = &bh[ni >> 1][(ni & 1) * 2];
                    const uint32_t* blp = &bl[ni >> 1][(ni & 1) * 2];
                    mma16816(acc[mi][ni], ah[mi], bhp);
                    mma16816(acc[mi][ni], al[mi], bhp);
                    mma16816(acc[mi][ni], ah[mi], blp);
                }
        }
        __syncthreads();
    }

    // ---- epilogue: bias + mask, direct global stores ----
    const float* bias = (mode == 0) ? bq : (mode == 1) ? bk_ : bv;
    float* __restrict__ C = (mode == 0) ? g_q : (mode == 1) ? g_k : g_v;
    const int rbase = (int)m0 + wm * 64 + (lane >> 2);
    const int cbase = n0 + wn * 32 + (lane & 3) * 2;
#pragma unroll
    for (int mi = 0; mi < 4; mi++) {
        const int r0 = rbase + mi * 16;
        const int r1 = r0 + 8;
        const float mk0 = mask[r0], mk1 = mask[r1];
        const float ma0 = (mode == 1) ? (1.0f - mk0) * NEGV : 0.f;
        const float ma1 = (mode == 1) ? (1.0f - mk1) * NEGV : 0.f;
        const float mm0 = (mode == 2) ? mk0 : 1.f;
        const float mm1 = (mode == 2) ? mk1 : 1.f;
#pragma unroll
        for (int ni = 0; ni < 4; ni++) {
            const int c = cbase + ni * 8;
            const float b0 = bias[c], b1 = bias[c + 1];
            float2 o0, o1;
            o0.x = (acc[mi][ni][0] + b0 + ma0) * mm0;
            o0.y = (acc[mi][ni][1] + b1 + ma0) * mm0;
            o1.x = (acc[mi][ni][2] + b0 + ma1) * mm1;
            o1.y = (acc[mi][ni][3] + b1 + ma1) * mm1;
            *(float2*)(C + (size_t)r0 * 1024 + c) = o0;
            *(float2*)(C + (size_t)r1 * 1024 + c) = o1;
        }
    }
}

// ---------------- q softmax over head-feature dim (128), one warp per row ---
__global__ void __launch_bounds__(256) qsoftmax_kernel() {
    const int idx = blockIdx.x * 8 + (threadIdx.x >> 5);
    const int lane = threadIdx.x & 31;
    float4* p = (float4*)(g_q + (size_t)idx * 128);
    float4 v = p[lane];
    float m = fmaxf(fmaxf(v.x, v.y), fmaxf(v.z, v.w));
#pragma unroll
    for (int o = 16; o > 0; o >>= 1) m = fmaxf(m, __shfl_xor_sync(0xffffffffu, m, o));
    v.x = __expf(v.x - m); v.y = __expf(v.y - m);
    v.z = __expf(v.z - m); v.w = __expf(v.w - m);
    float s = v.x + v.y + v.z + v.w;
#pragma unroll
    for (int o = 16; o > 0; o >>= 1) s += __shfl_xor_sync(0xffffffffu, s, o);
    const float inv = 1.0f / s;
    v.x *= inv; v.y *= inv; v.z *= inv; v.w *= inv;
    p[lane] = v;
}

// ---------------- k column max over time (2-pass) ----------------------------
__global__ void __launch_bounds__(256) kmax_part_kernel() {
    const int col = blockIdx.x * 256 + threadIdx.x;
    const int b = col >> 10, d = col & 1023;
    const float* base = g_k + ((size_t)b * T_) * D_ + d;
    const int t0 = blockIdx.y * 256;
    float m = -3.4e38f;
#pragma unroll 8
    for (int t = 0; t < 256; t++) m = fmaxf(m, base[(size_t)(t0 + t) * D_]);
    g_cmax_part[col * 16 + blockIdx.y] = m;
}

__global__ void __launch_bounds__(256) kmax_final_kernel() {
    const int col = blockIdx.x * 256 + threadIdx.x;
    float m = g_cmax_part[col * 16];
#pragma unroll
    for (int p = 1; p < 16; p++) m = fmaxf(m, g_cmax_part[col * 16 + p]);
    g_cmax[col] = m;
}

// ---------------- att partial: U[d][l] = sum_t exp(k-M)*v ; S[d] = sum exp ---
__global__ void __launch_bounds__(256) att_part_kernel() {
    __shared__ float Es[32][128];
    __shared__ float Vs[32][128];
    __shared__ float Ms[128];
    const int bh = blockIdx.x, sp = blockIdx.y;
    const int b = bh >> 3, h = bh & 7;
    const int tid = threadIdx.x;
    const int tx = tid & 15, ty = tid >> 4;
    if (tid < 128) Ms[tid] = g_cmax[b * 1024 + h * 128 + tid];
    __syncthreads();

    float acc[8][8];
#pragma unroll
    for (int i = 0; i < 8; i++)
#pragma unroll
        for (int j = 0; j < 8; j++) acc[i][j] = 0.f;
    float sacc[8];
#pragma unroll
    for (int i = 0; i < 8; i++) sacc[i] = 0.f;

    const size_t base = ((size_t)b * T_) * D_ + h * 128;
    for (int t0 = sp * 512; t0 < sp * 512 + 512; t0 += 32) {
#pragma unroll
        for (int s = 0; s < 4; s++) {
            const int idx = tid + s * 256;
            const int tr = idx >> 5, dc = (idx & 31) * 4;
            const size_t off = base + (size_t)(t0 + tr) * D_ + dc;
            const float4 kv = *(const float4*)(g_k + off);
            float4 e;
            e.x = __expf(kv.x - Ms[dc + 0]);
            e.y = __expf(kv.y - Ms[dc + 1]);
            e.z = __expf(kv.z - Ms[dc + 2]);
            e.w = __expf(kv.w - Ms[dc + 3]);
            *(float4*)&Es[tr][dc] = e;
            *(float4*)&Vs[tr][dc] = *(const float4*)(g_v + off);
        }
        __syncthreads();
#pragma unroll
        for (int kk = 0; kk < 32; kk++) {
            float a[8], bb[8];
            *(float4*)&a[0]  = *(float4*)&Es[kk][ty * 4];
            *(float4*)&a[4]  = *(float4*)&Es[kk][64 + ty * 4];
            *(float4*)&bb[0] = *(float4*)&Vs[kk][tx * 4];
            *(float4*)&bb[4] = *(float4*)&Vs[kk][64 + tx * 4];
#pragma unroll
            for (int i = 0; i < 8; i++)
#pragma unroll
                for (int j = 0; j < 8; j++) acc[i][j] += a[i] * bb[j];
            if (tx == 0) {
#pragma unroll
                for (int i = 0; i < 8; i++) sacc[i] += a[i];
            }
        }
        __syncthreads();
    }
    const size_t obase = ((size_t)sp * 32 + bh) * 16384;
#pragma unroll
    for (int i = 0; i < 8; i++) {
        const int r = (i < 4) ? (ty * 4 + i) : (64 + ty * 4 + i - 4);
#pragma unroll
        for (int jj = 0; jj < 2; jj++) {
            const int c = (jj == 0) ? (tx * 4) : (64 + tx * 4);
            float4 o;
            o.x = acc[i][jj * 4 + 0]; o.y = acc[i][jj * 4 + 1];
            o.z = acc[i][jj * 4 + 2]; o.w = acc[i][jj * 4 + 3];
            *(float4*)(g_attp + obase + (size_t)r * 128 + c) = o;
        }
        if (tx == 0) g_Sp[(size_t)sp * 4096 + bh * 128 + r] = sacc[i];
    }
}

// ---------------- att reduce: sum partials, normalize by S -------------------
__global__ void __launch_bounds__(256) att_reduce_kernel() {
    __shared__ float Ss[128];
    const int bh = blockIdx.x;
    const int tid = threadIdx.x;
    if (tid < 128) {
        float s = 0.f;
#pragma unroll
        for (int p = 0; p < 8; p++) s += g_Sp[(size_t)p * 4096 + bh * 128 + tid];
        Ss[tid] = 1.0f / s;
    }
    __syncthreads();
    for (int e = tid; e < 16384; e += 256) {
        const int d = e >> 7;
        float s = 0.f;
#pragma unroll
        for (int p = 0; p < 8; p++) s += g_attp[((size_t)p * 32 + bh) * 16384 + e];
        g_att[(size_t)bh * 16384 + e] = s * Ss[d];
    }
}

// ---------------- y = q_sm @ att, out = x + y -------------------------------
__global__ void __launch_bounds__(256) ygemm_kernel(const float* __restrict__ x,
                                                    float* __restrict__ out) {
    __shared__ float As[16][128];
    __shared__ float Bs[16][128];
    const int bh = blockIdx.y, mt = blockIdx.x;
    const int b = bh >> 3, h = bh & 7;
    const int tid = threadIdx.x;
    const int tx = tid & 15, ty = tid >> 4;
    const size_t qbase = ((size_t)b * T_ + mt * 128) * D_ + h * 128;
    const size_t attbase = (size_t)bh * 16384;

    float acc[8][8];
#pragma unroll
    for (int i = 0; i < 8; i++)
#pragma unroll
        for (int j = 0; j < 8; j++) acc[i][j] = 0.f;

    for (int k0 = 0; k0 < 128; k0 += 16) {
#pragma unroll
        for (int s = 0; s < 2; s++) {
            const int idx = tid + s * 256;
            const int ar = idx >> 2, ac = (idx & 3) * 4;
            const float4 a = *(const float4*)(g_q + qbase + (size_t)ar * D_ + k0 + ac);
            As[ac + 0][ar] = a.x; As[ac + 1][ar] = a.y;
            As[ac + 2][ar] = a.z; As[ac + 3][ar] = a.w;
            const int br = idx >> 5, bc = (idx & 31) * 4;
            *(float4*)&Bs[br][bc] =
                *(const float4*)(g_att + attbase + (size_t)(k0 + br) * 128 + bc);
        }
        __syncthreads();
#pragma unroll
        for (int kk = 0; kk < 16; kk++) {
            float a[8], bb[8];
            *(float4*)&a[0]  = *(float4*)&As[kk][ty * 4];
            *(float4*)&a[4]  = *(float4*)&As[kk][64 + ty * 4];
            *(float4*)&bb[0] = *(float4*)&Bs[kk][tx * 4];
            *(float4*)&bb[4] = *(float4*)&Bs[kk][64 + tx * 4];
#pragma unroll
            for (int i = 0; i < 8; i++)
#pragma unroll
                for (int j = 0; j < 8; j++) acc[i][j] += a[i] * bb[j];
        }
        __syncthreads();
    }
#pragma unroll
    for (int i = 0; i < 8; i++) {
        const int r = (i < 4) ? (ty * 4 + i) : (64 + ty * 4 + i - 4);
        const size_t row = (size_t)b * T_ + mt * 128 + r;
#pragma unroll
        for (int jj = 0; jj < 2; jj++) {
            const int c = (jj == 0) ? (tx * 4) : (64 + tx * 4);
            const size_t o = row * D_ + h * 128 + c;
            const float4 xres = *(const float4*)(x + o);
            float4 ov;
            ov.x = acc[i][jj * 4 + 0] + xres.x;
            ov.y = acc[i][jj * 4 + 1] + xres.y;
            ov.z = acc[i][jj * 4 + 2] + xres.z;
            ov.w = acc[i][jj * 4 + 3] + xres.w;
            *(float4*)(out + o) = ov;
        }
    }
}

// ---------------- launcher ---------------------------------------------------
extern "C" void kernel_launch(void* const* d_in, const int* in_sizes, int n_in,
                              void* d_out, int out_size) {
    const float* x     = (const float*)d_in[0];
    const float* mask  = (const float*)d_in[1];
    const float* Wq    = (const float*)d_in[2];
    const float* bq    = (const float*)d_in[3];
    const float* Wk    = (const float*)d_in[4];
    const float* bk    = (const float*)d_in[5];
    const float* Wv    = (const float*)d_in[6];
    const float* bv    = (const float*)d_in[7];
    const float* gamma = (const float*)d_in[8];
    const float* beta  = (const float*)d_in[9];
    float* out = (float*)d_out;

    static int smem_set = 0;
    if (!smem_set) {
        cudaFuncSetAttribute(qkv_mma, cudaFuncAttributeMaxDynamicSharedMemorySize,
                             QK_SMEM);
        smem_set = 1;
    }

    ln_kernel<<<NTOK, 256>>>(x, gamma, beta);
    wsplit_kernel<<<dim3(32, 32, 3), 256>>>(Wq, Wk, Wv);

    qkv_mma<<<dim3(8, 128, 3), 256, QK_SMEM>>>(bq, bk, bv, mask);

    qsoftmax_kernel<<<NTOK * H_ / 8, 256>>>();

    kmax_part_kernel<<<dim3(16, 16), 256>>>();
    kmax_final_kernel<<<16, 256>>>();

    att_part_kernel<<<dim3(32, 8), 256>>>();
    att_reduce_kernel<<<32, 256>>>();

    ygemm_kernel<<<dim3(32, 32), 256>>>(x, out);
}

// round 4
// speedup vs baseline: 2.6727x; 1.1608x over previous
#include <cuda_runtime.h>
#include <cuda_bf16.h>
#include <stdint.h>
#include <math.h>

#define B_ 4
#define T_ 4096
#define D_ 1024
#define H_ 8
#define DH_ 128
#define NTOK (B_ * T_)          // 16384
#define NEGV (-1000000.0f)
#define NSPLIT 16

// ---------------- scratch (device globals; no allocations allowed) ----------
__device__ __nv_bfloat16 g_xnh[(size_t)NTOK * D_];     // 32 MB  xn (bf16)
__device__ __nv_bfloat16 g_wth[(size_t)3 * D_ * D_];   // 6 MB   W^T hi (q,k,v)
__device__ __nv_bfloat16 g_wtl[(size_t)3 * D_ * D_];   // 6 MB   W^T lo
__device__ float g_q [(size_t)NTOK * D_];
__device__ float g_k [(size_t)NTOK * D_];
__device__ float g_v [(size_t)NTOK * D_];
__device__ float g_cmax_part[B_ * D_ * 16];
__device__ float g_cmax[B_ * D_];
__device__ float g_attp[(size_t)NSPLIT * B_ * H_ * DH_ * DH_];
__device__ float g_Sp[(size_t)NSPLIT * B_ * D_];
__device__ float g_att[(size_t)B_ * H_ * DH_ * DH_];

// ======================= PTX helpers (sm_103 baseline ISA only) ==============
__device__ __forceinline__ uint32_t smem_u32(const void* p) {
    uint32_t a;
    asm("{ .reg .u64 t; cvta.to.shared.u64 t, %1; cvt.u32.u64 %0, t; }"
        : "=r"(a) : "l"(p));
    return a;
}
__device__ __forceinline__ void cp16(uint32_t d, const void* g) {
    asm volatile("cp.async.cg.shared.global [%0], [%1], 16;" :: "r"(d), "l"(g));
}
#define CP_COMMIT()  asm volatile("cp.async.commit_group;")
#define CP_WAIT(n)   asm volatile("cp.async.wait_group %0;" :: "n"(n) : "memory")
#define SW128(o) ((uint32_t)(o) ^ ((((uint32_t)(o)) >> 3) & 0x70))

__device__ __forceinline__ void ldsm_x4(uint32_t& r0, uint32_t& r1,
                                        uint32_t& r2, uint32_t& r3, uint32_t a) {
    asm volatile("ldmatrix.sync.aligned.m8n8.x4.shared.b16 {%0,%1,%2,%3}, [%4];"
                 : "=r"(r0), "=r"(r1), "=r"(r2), "=r"(r3) : "r"(a));
}
__device__ __forceinline__ void mma16816(float* d, const uint32_t* a,
                                         const uint32_t* b) {
    asm volatile("mma.sync.aligned.m16n8k16.row.col.f32.bf16.bf16.f32 "
                 "{%0,%1,%2,%3}, {%4,%5,%6,%7}, {%8,%9}, {%0,%1,%2,%3};"
                 : "+f"(d[0]), "+f"(d[1]), "+f"(d[2]), "+f"(d[3])
                 : "r"(a[0]), "r"(a[1]), "r"(a[2]), "r"(a[3]),
                   "r"(b[0]), "r"(b[1]));
}

// ---------------- LayerNorm: one block per token; emits bf16 ----------------
__global__ void __launch_bounds__(256) ln_kernel(const float* __restrict__ x,
                                                 const float* __restrict__ gamma,
                                                 const float* __restrict__ beta) {
    __shared__ float red[16];
    const int row = blockIdx.x;
    const int tid = threadIdx.x;
    const float4 v = ((const float4*)(x + (size_t)row * D_))[tid];
    float s  = v.x + v.y + v.z + v.w;
    float ss = v.x * v.x + v.y * v.y + v.z * v.z + v.w * v.w;
#pragma unroll
    for (int o = 16; o > 0; o >>= 1) {
        s  += __shfl_xor_sync(0xffffffffu, s, o);
        ss += __shfl_xor_sync(0xffffffffu, ss, o);
    }
    const int warp = tid >> 5, lane = tid & 31;
    if (lane == 0) { red[warp] = s; red[warp + 8] = ss; }
    __syncthreads();
    if (tid < 32) {
        float a = (tid < 8) ? red[tid] : 0.f;
        float b = (tid < 8) ? red[tid + 8] : 0.f;
#pragma unroll
        for (int o = 4; o > 0; o >>= 1) {
            a += __shfl_xor_sync(0xffffffffu, a, o);
            b += __shfl_xor_sync(0xffffffffu, b, o);
        }
        if (tid == 0) { red[0] = a; red[1] = b; }
    }
    __syncthreads();
    const float mu   = red[0] * (1.0f / D_);
    const float var  = red[1] * (1.0f / D_) - mu * mu;
    const float rstd = rsqrtf(var + 1e-5f);
    const float4 g  = ((const float4*)gamma)[tid];
    const float4 bb = ((const float4*)beta)[tid];
    float o0 = (v.x - mu) * rstd * g.x + bb.x;
    float o1 = (v.y - mu) * rstd * g.y + bb.y;
    float o2 = (v.z - mu) * rstd * g.z + bb.z;
    float o3 = (v.w - mu) * rstd * g.w + bb.w;
    const size_t off = (size_t)row * D_ + tid * 4;
    *(__nv_bfloat162*)(g_xnh + off)     = __floats2bfloat162_rn(o0, o1);
    *(__nv_bfloat162*)(g_xnh + off + 2) = __floats2bfloat162_rn(o2, o3);
}

// ---------------- W transpose + hi/lo split: Wt[n][k] = W[k][n] --------------
__global__ void __launch_bounds__(256) wsplit_kernel(const float* __restrict__ Wq,
                                                     const float* __restrict__ Wk,
                                                     const float* __restrict__ Wv) {
    __shared__ float t[32][33];
    const float* W = (blockIdx.z == 0) ? Wq : (blockIdx.z == 1) ? Wk : Wv;
    __nv_bfloat16* oh = g_wth + ((size_t)blockIdx.z << 20);
    __nv_bfloat16* ol = g_wtl + ((size_t)blockIdx.z << 20);
    const int tid = threadIdx.x;
    const int tx = tid & 31, ty = tid >> 5;
    const int bn = blockIdx.x * 32, bk = blockIdx.y * 32;
#pragma unroll
    for (int r = ty; r < 32; r += 8)
        t[r][tx] = W[(size_t)(bk + r) * 1024 + bn + tx];
    __syncthreads();
#pragma unroll
    for (int r = ty; r < 32; r += 8) {
        const float v = t[tx][r];                 // = W[bk+tx][bn+r]
        const __nv_bfloat16 h = __float2bfloat16_rn(v);
        const __nv_bfloat16 l = __float2bfloat16_rn(v - __bfloat162float(h));
        const size_t o = (size_t)(bn + r) * 1024 + bk + tx;
        oh[o] = h; ol[o] = l;
    }
}

// ---------------- QKV GEMM via mma.sync bf16, 2-term split (W hi/lo) ---------
// Tile 128(M) x 256(N), BK=64, 2-stage cp.async, 512 threads.
// 16 warps: warp (wm 0..3, wn 0..3) owns 32x64.
// grid (4 n-tiles, 128 m-tiles, 3 modes). mode 0:q 1:k 2:v.
#define OFF_A  0
#define OFF_BH 16384
#define OFF_BL 49152
#define STG    81920
#define QK_SMEM (2 * STG + 1024)

__global__ void __launch_bounds__(512, 1)
qkv_mma(const float* __restrict__ bq, const float* __restrict__ bk_,
        const float* __restrict__ bv, const float* __restrict__ mask) {
    extern __shared__ char dsm[];
    const uint32_t base = (smem_u32(dsm) + 1023) & ~1023u;
    const int tid = threadIdx.x, lane = tid & 31, wid = tid >> 5;
    const int wm = wid & 3, wn = wid >> 2;
    const int mode = blockIdx.z;
    const int n0 = blockIdx.x * 256;
    const size_t m0 = (size_t)blockIdx.y * 128;

    const __nv_bfloat16* A  = g_xnh;
    const __nv_bfloat16* Bh = g_wth + ((size_t)mode << 20);
    const __nv_bfloat16* Bl = g_wtl + ((size_t)mode << 20);

    float acc[2][8][4];
#pragma unroll
    for (int i = 0; i < 2; i++)
#pragma unroll
        for (int j = 0; j < 8; j++)
#pragma unroll
            for (int q = 0; q < 4; q++) acc[i][j][q] = 0.f;

    // ---- stage loader: A 128x64, Bh/Bl 256x64 ----
    auto issue = [&](int i) {
        const int k0 = i * 64;
        const uint32_t sb = base + (i & 1) * STG;
#pragma unroll
        for (int p = 0; p < 2; p++) {
            const int idx = p * 512 + tid;             // 0..1023
            const int r = idx >> 3, kc = idx & 7;
            const uint32_t sw = SW128(r * 128 + kc * 16);
            cp16(sb + OFF_A + sw, A + (m0 + r) * 1024 + k0 + kc * 8);
        }
#pragma unroll
        for (int p = 0; p < 4; p++) {
            const int idx = p * 512 + tid;             // 0..2047
            const int r = idx >> 3, kc = idx & 7;
            const uint32_t sw = SW128(r * 128 + kc * 16);
            const size_t gb = (size_t)(n0 + r) * 1024 + k0 + kc * 8;
            cp16(sb + OFF_BH + sw, Bh + gb);
            cp16(sb + OFF_BL + sw, Bl + gb);
        }
        CP_COMMIT();
    };

    issue(0);
    const int arow  = wm * 32 + (lane & 15);
    const int acolb = (lane >> 4) * 16;
    const int brow  = wn * 64 + (lane & 7) + ((lane & 16) ? 8 : 0);
    const int bcolb = (lane & 8) ? 16 : 0;

    for (int i = 0; i < 16; i++) {
        if (i + 1 < 16) { issue(i + 1); CP_WAIT(1); }
        else            { CP_WAIT(0); }
        __syncthreads();
        const uint32_t sb = base + (i & 1) * STG;

#pragma unroll
        for (int ks = 0; ks < 4; ks++) {
            const int kb = ks * 32;
            uint32_t ah[2][4];
#pragma unroll
            for (int mi = 0; mi < 2; mi++) {
                const uint32_t ao = SW128((arow + mi * 16) * 128 + kb + acolb);
                ldsm_x4(ah[mi][0], ah[mi][1], ah[mi][2], ah[mi][3],
                        sb + OFF_A + ao);
            }
#pragma unroll
            for (int nb = 0; nb < 4; nb++) {
                const uint32_t bo = SW128((brow + nb * 16) * 128 + kb + bcolb);
                uint32_t bh[4], bl[4];
                ldsm_x4(bh[0], bh[1], bh[2], bh[3], sb + OFF_BH + bo);
                ldsm_x4(bl[0], bl[1], bl[2], bl[3], sb + OFF_BL + bo);
#pragma unroll
                for (int mi = 0; mi < 2; mi++)
#pragma unroll
                    for (int ns = 0; ns < 2; ns++) {
                        const int ni = nb * 2 + ns;
                        mma16816(acc[mi][ni], ah[mi], &bh[ns * 2]);
                        mma16816(acc[mi][ni], ah[mi], &bl[ns * 2]);
                    }
            }
        }
        __syncthreads();
    }

    // ---- epilogue: bias + mask, direct global stores ----
    const float* bias = (mode == 0) ? bq : (mode == 1) ? bk_ : bv;
    float* __restrict__ C = (mode == 0) ? g_q : (mode == 1) ? g_k : g_v;
    const int rbase = (int)m0 + wm * 32 + (lane >> 2);
    const int cbase = n0 + wn * 64 + (lane & 3) * 2;
#pragma unroll
    for (int mi = 0; mi < 2; mi++) {
        const int r0 = rbase + mi * 16;
        const int r1 = r0 + 8;
        const float mk0 = mask[r0], mk1 = mask[r1];
        const float ma0 = (mode == 1) ? (1.0f - mk0) * NEGV : 0.f;
        const float ma1 = (mode == 1) ? (1.0f - mk1) * NEGV : 0.f;
        const float mm0 = (mode == 2) ? mk0 : 1.f;
        const float mm1 = (mode == 2) ? mk1 : 1.f;
#pragma unroll
        for (int ni = 0; ni < 8; ni++) {
            const int c = cbase + ni * 8;
            const float b0 = bias[c], b1 = bias[c + 1];
            float2 o0, o1;
            o0.x = (acc[mi][ni][0] + b0 + ma0) * mm0;
            o0.y = (acc[mi][ni][1] + b1 + ma0) * mm0;
            o1.x = (acc[mi][ni][2] + b0 + ma1) * mm1;
            o1.y = (acc[mi][ni][3] + b1 + ma1) * mm1;
            *(float2*)(C + (size_t)r0 * 1024 + c) = o0;
            *(float2*)(C + (size_t)r1 * 1024 + c) = o1;
        }
    }
}

// ---------------- q softmax over head-feature dim (128), one warp per row ---
__global__ void __launch_bounds__(256) qsoftmax_kernel() {
    const int idx = blockIdx.x * 8 + (threadIdx.x >> 5);
    const int lane = threadIdx.x & 31;
    float4* p = (float4*)(g_q + (size_t)idx * 128);
    float4 v = p[lane];
    float m = fmaxf(fmaxf(v.x, v.y), fmaxf(v.z, v.w));
#pragma unroll
    for (int o = 16; o > 0; o >>= 1) m = fmaxf(m, __shfl_xor_sync(0xffffffffu, m, o));
    v.x = __expf(v.x - m); v.y = __expf(v.y - m);
    v.z = __expf(v.z - m); v.w = __expf(v.w - m);
    float s = v.x + v.y + v.z + v.w;
#pragma unroll
    for (int o = 16; o > 0; o >>= 1) s += __shfl_xor_sync(0xffffffffu, s, o);
    const float inv = 1.0f / s;
    v.x *= inv; v.y *= inv; v.z *= inv; v.w *= inv;
    p[lane] = v;
}

// ---------------- k column max over time (2-pass) ----------------------------
__global__ void __launch_bounds__(256) kmax_part_kernel() {
    const int col = blockIdx.x * 256 + threadIdx.x;
    const int b = col >> 10, d = col & 1023;
    const float* base = g_k + ((size_t)b * T_) * D_ + d;
    const int t0 = blockIdx.y * 256;
    float m = -3.4e38f;
#pragma unroll 8
    for (int t = 0; t < 256; t++) m = fmaxf(m, base[(size_t)(t0 + t) * D_]);
    g_cmax_part[col * 16 + blockIdx.y] = m;
}

__global__ void __launch_bounds__(256) kmax_final_kernel() {
    const int col = blockIdx.x * 256 + threadIdx.x;
    float m = g_cmax_part[col * 16];
#pragma unroll
    for (int p = 1; p < 16; p++) m = fmaxf(m, g_cmax_part[col * 16 + p]);
    g_cmax[col] = m;
}

// ---------------- att partial: U[d][l] = sum_t exp(k-M)*v ; S[d] = sum exp ---
// grid (bh=32, split=16); each block: 128x128 output over 256 timesteps.
// Masked timesteps (mask==0) contribute exactly 0 (exp(-1e6)=0, v=0):
// skip exp/loads for them; skip FFMA when the whole 32-t tile is masked.
__global__ void __launch_bounds__(256) att_part_kernel(const float* __restrict__ mask) {
    __shared__ float Es[32][128];
    __shared__ float Vs[32][128];
    __shared__ float Ms[128];
    const int bh = blockIdx.x, sp = blockIdx.y;
    const int b = bh >> 3, h = bh & 7;
    const int tid = threadIdx.x;
    const int tx = tid & 15, ty = tid >> 4;
    if (tid < 128) Ms[tid] = g_cmax[b * 1024 + h * 128 + tid];
    __syncthreads();

    float acc[8][8];
#pragma unroll
    for (int i = 0; i < 8; i++)
#pragma unroll
        for (int j = 0; j < 8; j++) acc[i][j] = 0.f;
    float sacc[8];
#pragma unroll
    for (int i = 0; i < 8; i++) sacc[i] = 0.f;

    const size_t base = ((size_t)b * T_) * D_ + h * 128;
    const int tstart = sp * (T_ / NSPLIT);
    for (int t0 = tstart; t0 < tstart + T_ / NSPLIT; t0 += 32) {
        int myvalid = 0;
#pragma unroll
        for (int s = 0; s < 4; s++) {
            const int idx = tid + s * 256;
            const int tr = idx >> 5, dc = (idx & 31) * 4;   // tr warp-uniform
            const float mk = mask[b * T_ + t0 + tr];
            if (mk != 0.f) {
                myvalid = 1;
                const size_t off = base + (size_t)(t0 + tr) * D_ + dc;
                const float4 kv = *(const float4*)(g_k + off);
                float4 e;
                e.x = __expf(kv.x - Ms[dc + 0]);
                e.y = __expf(kv.y - Ms[dc + 1]);
                e.z = __expf(kv.z - Ms[dc + 2]);
                e.w = __expf(kv.w - Ms[dc + 3]);
                *(float4*)&Es[tr][dc] = e;
                *(float4*)&Vs[tr][dc] = *(const float4*)(g_v + off);
            } else {
                *(float4*)&Es[tr][dc] = make_float4(0.f, 0.f, 0.f, 0.f);
                *(float4*)&Vs[tr][dc] = make_float4(0.f, 0.f, 0.f, 0.f);
            }
        }
        const int anyvalid = __syncthreads_or(myvalid);
        if (anyvalid) {
#pragma unroll
            for (int kk = 0; kk < 32; kk++) {
                float a[8], bb[8];
                *(float4*)&a[0]  = *(float4*)&Es[kk][ty * 4];
                *(float4*)&a[4]  = *(float4*)&Es[kk][64 + ty * 4];
                *(float4*)&bb[0] = *(float4*)&Vs[kk][tx * 4];
                *(float4*)&bb[4] = *(float4*)&Vs[kk][64 + tx * 4];
#pragma unroll
                for (int i = 0; i < 8; i++)
#pragma unroll
                    for (int j = 0; j < 8; j++) acc[i][j] += a[i] * bb[j];
                if (tx == 0) {
#pragma unroll
                    for (int i = 0; i < 8; i++) sacc[i] += a[i];
                }
            }
        }
        __syncthreads();
    }
    const size_t obase = ((size_t)sp * 32 + bh) * 16384;
#pragma unroll
    for (int i = 0; i < 8; i++) {
        const int r = (i < 4) ? (ty * 4 + i) : (64 + ty * 4 + i - 4);
#pragma unroll
        for (int jj = 0; jj < 2; jj++) {
            const int c = (jj == 0) ? (tx * 4) : (64 + tx * 4);
            float4 o;
            o.x = acc[i][jj * 4 + 0]; o.y = acc[i][jj * 4 + 1];
            o.z = acc[i][jj * 4 + 2]; o.w = acc[i][jj * 4 + 3];
            *(float4*)(g_attp + obase + (size_t)r * 128 + c) = o;
        }
        if (tx == 0) g_Sp[(size_t)sp * 4096 + bh * 128 + r] = sacc[i];
    }
}

// ---------------- att reduce: sum partials, normalize by S -------------------
__global__ void __launch_bounds__(256) att_reduce_kernel() {
    __shared__ float Ss[128];
    const int bh = blockIdx.x;
    const int tid = threadIdx.x;
    if (tid < 128) {
        float s = 0.f;
#pragma unroll
        for (int p = 0; p < NSPLIT; p++) s += g_Sp[(size_t)p * 4096 + bh * 128 + tid];
        Ss[tid] = 1.0f / s;
    }
    __syncthreads();
    for (int e = tid; e < 16384; e += 256) {
        const int d = e >> 7;
        float s = 0.f;
#pragma unroll
        for (int p = 0; p < NSPLIT; p++) s += g_attp[((size_t)p * 32 + bh) * 16384 + e];
        g_att[(size_t)bh * 16384 + e] = s * Ss[d];
    }
}

// ---------------- y = q_sm @ att, out = x + y -------------------------------
__global__ void __launch_bounds__(256) ygemm_kernel(const float* __restrict__ x,
                                                    float* __restrict__ out) {
    __shared__ float As[16][128];
    __shared__ float Bs[16][128];
    const int bh = blockIdx.y, mt = blockIdx.x;
    const int b = bh >> 3, h = bh & 7;
    const int tid = threadIdx.x;
    const int tx = tid & 15, ty = tid >> 4;
    const size_t qbase = ((size_t)b * T_ + mt * 128) * D_ + h * 128;
    const size_t attbase = (size_t)bh * 16384;

    float acc[8][8];
#pragma unroll
    for (int i = 0; i < 8; i++)
#pragma unroll
        for (int j = 0; j < 8; j++) acc[i][j] = 0.f;

    for (int k0 = 0; k0 < 128; k0 += 16) {
#pragma unroll
        for (int s = 0; s < 2; s++) {
            const int idx = tid + s * 256;
            const int ar = idx >> 2, ac = (idx & 3) * 4;
            const float4 a = *(const float4*)(g_q + qbase + (size_t)ar * D_ + k0 + ac);
            As[ac + 0][ar] = a.x; As[ac + 1][ar] = a.y;
            As[ac + 2][ar] = a.z; As[ac + 3][ar] = a.w;
            const int br = idx >> 5, bc = (idx & 31) * 4;
            *(float4*)&Bs[br][bc] =
                *(const float4*)(g_att + attbase + (size_t)(k0 + br) * 128 + bc);
        }
        __syncthreads();
#pragma unroll
        for (int kk = 0; kk < 16; kk++) {
            float a[8], bb[8];
            *(float4*)&a[0]  = *(float4*)&As[kk][ty * 4];
            *(float4*)&a[4]  = *(float4*)&As[kk][64 + ty * 4];
            *(float4*)&bb[0] = *(float4*)&Bs[kk][tx * 4];
            *(float4*)&bb[4] = *(float4*)&Bs[kk][64 + tx * 4];
#pragma unroll
            for (int i = 0; i < 8; i++)
#pragma unroll
                for (int j = 0; j < 8; j++) acc[i][j] += a[i] * bb[j];
        }
        __syncthreads();
    }
#pragma unroll
    for (int i = 0; i < 8; i++) {
        const int r = (i < 4) ? (ty * 4 + i) : (64 + ty * 4 + i - 4);
        const size_t row = (size_t)b * T_ + mt * 128 + r;
#pragma unroll
        for (int jj = 0; jj < 2; jj++) {
            const int c = (jj == 0) ? (tx * 4) : (64 + tx * 4);
            const size_t o = row * D_ + h * 128 + c;
            const float4 xres = *(const float4*)(x + o);
            float4 ov;
            ov.x = acc[i][jj * 4 + 0] + xres.x;
            ov.y = acc[i][jj * 4 + 1] + xres.y;
            ov.z = acc[i][jj * 4 + 2] + xres.z;
            ov.w = acc[i][jj * 4 + 3] + xres.w;
            *(float4*)(out + o) = ov;
        }
    }
}

// ---------------- launcher ---------------------------------------------------
extern "C" void kernel_launch(void* const* d_in, const int* in_sizes, int n_in,
                              void* d_out, int out_size) {
    const float* x     = (const float*)d_in[0];
    const float* mask  = (const float*)d_in[1];
    const float* Wq    = (const float*)d_in[2];
    const float* bq    = (const float*)d_in[3];
    const float* Wk    = (const float*)d_in[4];
    const float* bk    = (const float*)d_in[5];
    const float* Wv    = (const float*)d_in[6];
    const float* bv    = (const float*)d_in[7];
    const float* gamma = (const float*)d_in[8];
    const float* beta  = (const float*)d_in[9];
    float* out = (float*)d_out;

    static int smem_set = 0;
    if (!smem_set) {
        cudaFuncSetAttribute(qkv_mma, cudaFuncAttributeMaxDynamicSharedMemorySize,
                             QK_SMEM);
        smem_set = 1;
    }

    ln_kernel<<<NTOK, 256>>>(x, gamma, beta);
    wsplit_kernel<<<dim3(32, 32, 3), 256>>>(Wq, Wk, Wv);

    qkv_mma<<<dim3(4, 128, 3), 512, QK_SMEM>>>(bq, bk, bv, mask);

    qsoftmax_kernel<<<NTOK * H_ / 8, 256>>>();

    kmax_part_kernel<<<dim3(16, 16), 256>>>();
    kmax_final_kernel<<<16, 256>>>();

    att_part_kernel<<<dim3(32, NSPLIT), 256>>>(mask);
    att_reduce_kernel<<<32, 256>>>();

    ygemm_kernel<<<dim3(32, 32), 256>>>(x, out);
}

// round 5
// speedup vs baseline: 4.6710x; 1.7477x over previous
#include <cuda_runtime.h>
#include <cuda_bf16.h>
#include <stdint.h>
#include <math.h>

#define B_ 4
#define T_ 4096
#define D_ 1024
#define H_ 8
#define DH_ 128
#define NTOK (B_ * T_)          // 16384
#define NEGV (-1000000.0f)
#define NSPLIT 16
#define EP 272                  // padded smem row stride (bytes) for 128 bf16

// ---------------- scratch (device globals; no allocations allowed) ----------
__device__ __nv_bfloat16 g_xnh[(size_t)NTOK * D_];     // 32 MB xn (bf16)
__device__ __nv_bfloat16 g_wth[(size_t)3 * D_ * D_];   // 6 MB  W^T (q,k,v) bf16
__device__ float g_q [(size_t)NTOK * D_];              // 64 MB
__device__ float g_k [(size_t)NTOK * D_];              // 64 MB
__device__ float g_v [(size_t)NTOK * D_];              // 64 MB
__device__ __nv_bfloat16 g_qb[(size_t)NTOK * D_];      // 32 MB q softmaxed bf16
__device__ float g_cmax_part[B_ * D_ * 16];
__device__ float g_cmax[B_ * D_];
__device__ float g_attp[(size_t)NSPLIT * B_ * H_ * DH_ * DH_];  // 32 MB
__device__ float g_Sp[(size_t)NSPLIT * B_ * D_];
__device__ __nv_bfloat16 g_attb[(size_t)B_ * H_ * DH_ * DH_];   // 1 MB

// ======================= PTX helpers (sm_103 baseline ISA only) ==============
__device__ __forceinline__ uint32_t smem_u32(const void* p) {
    uint32_t a;
    asm("{ .reg .u64 t; cvta.to.shared.u64 t, %1; cvt.u32.u64 %0, t; }"
        : "=r"(a) : "l"(p));
    return a;
}
__device__ __forceinline__ void cp16(uint32_t d, const void* g) {
    asm volatile("cp.async.cg.shared.global [%0], [%1], 16;" :: "r"(d), "l"(g));
}
#define CP_COMMIT()  asm volatile("cp.async.commit_group;")
#define CP_WAIT(n)   asm volatile("cp.async.wait_group %0;" :: "n"(n) : "memory")
#define SW128(o) ((uint32_t)(o) ^ ((((uint32_t)(o)) >> 3) & 0x70))

__device__ __forceinline__ void ldsm_x4(uint32_t* r, uint32_t a) {
    asm volatile("ldmatrix.sync.aligned.m8n8.x4.shared.b16 {%0,%1,%2,%3}, [%4];"
                 : "=r"(r[0]), "=r"(r[1]), "=r"(r[2]), "=r"(r[3]) : "r"(a));
}
__device__ __forceinline__ void ldsm_x4t(uint32_t* r, uint32_t a) {
    asm volatile("ldmatrix.sync.aligned.m8n8.x4.trans.shared.b16 {%0,%1,%2,%3}, [%4];"
                 : "=r"(r[0]), "=r"(r[1]), "=r"(r[2]), "=r"(r[3]) : "r"(a));
}
__device__ __forceinline__ void mma16816(float* d, const uint32_t* a,
                                         const uint32_t* b) {
    asm volatile("mma.sync.aligned.m16n8k16.row.col.f32.bf16.bf16.f32 "
                 "{%0,%1,%2,%3}, {%4,%5,%6,%7}, {%8,%9}, {%0,%1,%2,%3};"
                 : "+f"(d[0]), "+f"(d[1]), "+f"(d[2]), "+f"(d[3])
                 : "r"(a[0]), "r"(a[1]), "r"(a[2]), "r"(a[3]),
                   "r"(b[0]), "r"(b[1]));
}

// ---------------- LayerNorm: one block per token; emits bf16 ----------------
__global__ void __launch_bounds__(256) ln_kernel(const float* __restrict__ x,
                                                 const float* __restrict__ gamma,
                                                 const float* __restrict__ beta) {
    __shared__ float red[16];
    const int row = blockIdx.x;
    const int tid = threadIdx.x;
    const float4 v = ((const float4*)(x + (size_t)row * D_))[tid];
    float s  = v.x + v.y + v.z + v.w;
    float ss = v.x * v.x + v.y * v.y + v.z * v.z + v.w * v.w;
#pragma unroll
    for (int o = 16; o > 0; o >>= 1) {
        s  += __shfl_xor_sync(0xffffffffu, s, o);
        ss += __shfl_xor_sync(0xffffffffu, ss, o);
    }
    const int warp = tid >> 5, lane = tid & 31;
    if (lane == 0) { red[warp] = s; red[warp + 8] = ss; }
    __syncthreads();
    if (tid < 32) {
        float a = (tid < 8) ? red[tid] : 0.f;
        float b = (tid < 8) ? red[tid + 8] : 0.f;
#pragma unroll
        for (int o = 4; o > 0; o >>= 1) {
            a += __shfl_xor_sync(0xffffffffu, a, o);
            b += __shfl_xor_sync(0xffffffffu, b, o);
        }
        if (tid == 0) { red[0] = a; red[1] = b; }
    }
    __syncthreads();
    const float mu   = red[0] * (1.0f / D_);
    const float var  = red[1] * (1.0f / D_) - mu * mu;
    const float rstd = rsqrtf(var + 1e-5f);
    const float4 g  = ((const float4*)gamma)[tid];
    const float4 bb = ((const float4*)beta)[tid];
    const float o0 = (v.x - mu) * rstd * g.x + bb.x;
    const float o1 = (v.y - mu) * rstd * g.y + bb.y;
    const float o2 = (v.z - mu) * rstd * g.z + bb.z;
    const float o3 = (v.w - mu) * rstd * g.w + bb.w;
    const size_t off = (size_t)row * D_ + tid * 4;
    *(__nv_bfloat162*)(g_xnh + off)     = __floats2bfloat162_rn(o0, o1);
    *(__nv_bfloat162*)(g_xnh + off + 2) = __floats2bfloat162_rn(o2, o3);
}

// ---------------- W transpose to bf16: Wt[n][k] = W[k][n] --------------------
__global__ void __launch_bounds__(256) wsplit_kernel(const float* __restrict__ Wq,
                                                     const float* __restrict__ Wk,
                                                     const float* __restrict__ Wv) {
    __shared__ float t[32][33];
    const float* W = (blockIdx.z == 0) ? Wq : (blockIdx.z == 1) ? Wk : Wv;
    __nv_bfloat16* oh = g_wth + ((size_t)blockIdx.z << 20);
    const int tid = threadIdx.x;
    const int tx = tid & 31, ty = tid >> 5;
    const int bn = blockIdx.x * 32, bk = blockIdx.y * 32;
#pragma unroll
    for (int r = ty; r < 32; r += 8)
        t[r][tx] = W[(size_t)(bk + r) * 1024 + bn + tx];
    __syncthreads();
#pragma unroll
    for (int r = ty; r < 32; r += 8)
        oh[(size_t)(bn + r) * 1024 + bk + tx] = __float2bfloat16_rn(t[tx][r]);
}

// ---------------- QKV GEMM via mma.sync bf16 (single term) -------------------
// Tile 128(M) x 256(N), BK=64, 3-stage cp.async, 512 threads.
// 16 warps: warp (wm 0..3, wn 0..3) owns 32x64.
#define OFF_A  0
#define OFF_B  16384
#define STG    49152
#define QK_SMEM (3 * STG + 1024)

__global__ void __launch_bounds__(512, 1)
qkv_mma(const float* __restrict__ bq, const float* __restrict__ bk_,
        const float* __restrict__ bv, const float* __restrict__ mask) {
    extern __shared__ char dsm[];
    const uint32_t base = (smem_u32(dsm) + 1023) & ~1023u;
    const int tid = threadIdx.x, lane = tid & 31, wid = tid >> 5;
    const int wm = wid & 3, wn = wid >> 2;
    const int mode = blockIdx.z;
    const int n0 = blockIdx.x * 256;
    const size_t m0 = (size_t)blockIdx.y * 128;

    const __nv_bfloat16* A = g_xnh;
    const __nv_bfloat16* Bw = g_wth + ((size_t)mode << 20);

    float acc[2][8][4];
#pragma unroll
    for (int i = 0; i < 2; i++)
#pragma unroll
        for (int j = 0; j < 8; j++)
#pragma unroll
            for (int q = 0; q < 4; q++) acc[i][j][q] = 0.f;

    auto issue = [&](int i) {
        const int k0 = i * 64;
        const uint32_t sb = base + (i % 3) * STG;
#pragma unroll
        for (int p = 0; p < 2; p++) {
            const int idx = p * 512 + tid;             // 0..1023
            const int r = idx >> 3, kc = idx & 7;
            const uint32_t sw = SW128(r * 128 + kc * 16);
            cp16(sb + OFF_A + sw, A + (m0 + r) * 1024 + k0 + kc * 8);
        }
#pragma unroll
        for (int p = 0; p < 4; p++) {
            const int idx = p * 512 + tid;             // 0..2047
            const int r = idx >> 3, kc = idx & 7;
            const uint32_t sw = SW128(r * 128 + kc * 16);
            cp16(sb + OFF_B + sw, Bw + (size_t)(n0 + r) * 1024 + k0 + kc * 8);
        }
        CP_COMMIT();
    };

    issue(0); issue(1);
    const int arow  = wm * 32 + (lane & 15);
    const int acolb = (lane >> 4) * 16;
    const int brow  = wn * 64 + (lane & 7) + ((lane & 16) ? 8 : 0);
    const int bcolb = (lane & 8) ? 16 : 0;

    for (int i = 0; i < 16; i++) {
        if (i + 2 < 16)      { issue(i + 2); CP_WAIT(2); }
        else if (i + 1 < 16) { CP_WAIT(1); }
        else                 { CP_WAIT(0); }
        __syncthreads();
        const uint32_t sb = base + (i % 3) * STG;

#pragma unroll
        for (int ks = 0; ks < 4; ks++) {
            const int kb = ks * 32;
            uint32_t ah[2][4];
#pragma unroll
            for (int mi = 0; mi < 2; mi++) {
                const uint32_t ao = SW128((arow + mi * 16) * 128 + kb + acolb);
                ldsm_x4(ah[mi], sb + OFF_A + ao);
            }
#pragma unroll
            for (int nb = 0; nb < 4; nb++) {
                const uint32_t bo = SW128((brow + nb * 16) * 128 + kb + bcolb);
                uint32_t bh[4];
                ldsm_x4(bh, sb + OFF_B + bo);
#pragma unroll
                for (int mi = 0; mi < 2; mi++)
#pragma unroll
                    for (int ns = 0; ns < 2; ns++)
                        mma16816(acc[mi][nb * 2 + ns], ah[mi], &bh[ns * 2]);
            }
        }
        __syncthreads();
    }

    // ---- epilogue: bias + mask, direct global stores ----
    const float* bias = (mode == 0) ? bq : (mode == 1) ? bk_ : bv;
    float* __restrict__ C = (mode == 0) ? g_q : (mode == 1) ? g_k : g_v;
    const int rbase = (int)m0 + wm * 32 + (lane >> 2);
    const int cbase = n0 + wn * 64 + (lane & 3) * 2;
#pragma unroll
    for (int mi = 0; mi < 2; mi++) {
        const int r0 = rbase + mi * 16;
        const int r1 = r0 + 8;
        const float mk0 = mask[r0], mk1 = mask[r1];
        const float ma0 = (mode == 1) ? (1.0f - mk0) * NEGV : 0.f;
        const float ma1 = (mode == 1) ? (1.0f - mk1) * NEGV : 0.f;
        const float mm0 = (mode == 2) ? mk0 : 1.f;
        const float mm1 = (mode == 2) ? mk1 : 1.f;
#pragma unroll
        for (int ni = 0; ni < 8; ni++) {
            const int c = cbase + ni * 8;
            const float b0 = bias[c], b1 = bias[c + 1];
            float2 o0, o1;
            o0.x = (acc[mi][ni][0] + b0 + ma0) * mm0;
            o0.y = (acc[mi][ni][1] + b1 + ma0) * mm0;
            o1.x = (acc[mi][ni][2] + b0 + ma1) * mm1;
            o1.y = (acc[mi][ni][3] + b1 + ma1) * mm1;
            *(float2*)(C + (size_t)r0 * 1024 + c) = o0;
            *(float2*)(C + (size_t)r1 * 1024 + c) = o1;
        }
    }
}

// ---------------- q softmax over head-feature dim (128) -> bf16 -------------
__global__ void __launch_bounds__(256) qsoftmax_kernel() {
    const int idx = blockIdx.x * 8 + (threadIdx.x >> 5);  // token*8 + head
    const int lane = threadIdx.x & 31;
    const float4 v0 = ((const float4*)(g_q + (size_t)idx * 128))[lane];
    float4 v = v0;
    float m = fmaxf(fmaxf(v.x, v.y), fmaxf(v.z, v.w));
#pragma unroll
    for (int o = 16; o > 0; o >>= 1) m = fmaxf(m, __shfl_xor_sync(0xffffffffu, m, o));
    v.x = __expf(v.x - m); v.y = __expf(v.y - m);
    v.z = __expf(v.z - m); v.w = __expf(v.w - m);
    float s = v.x + v.y + v.z + v.w;
#pragma unroll
    for (int o = 16; o > 0; o >>= 1) s += __shfl_xor_sync(0xffffffffu, s, o);
    const float inv = 1.0f / s;
    __nv_bfloat162 p01 = __floats2bfloat162_rn(v.x * inv, v.y * inv);
    __nv_bfloat162 p23 = __floats2bfloat162_rn(v.z * inv, v.w * inv);
    uint2 pk;
    pk.x = *(uint32_t*)&p01; pk.y = *(uint32_t*)&p23;
    *(uint2*)(g_qb + (size_t)idx * 128 + lane * 4) = pk;
}

// ---------------- k column max over time (2-pass) ----------------------------
__global__ void __launch_bounds__(256) kmax_part_kernel() {
    const int col = blockIdx.x * 256 + threadIdx.x;
    const int b = col >> 10, d = col & 1023;
    const float* base = g_k + ((size_t)b * T_) * D_ + d;
    const int t0 = blockIdx.y * 256;
    float m = -3.4e38f;
#pragma unroll 8
    for (int t = 0; t < 256; t++) m = fmaxf(m, base[(size_t)(t0 + t) * D_]);
    g_cmax_part[col * 16 + blockIdx.y] = m;
}

__global__ void __launch_bounds__(256) kmax_final_kernel() {
    const int col = blockIdx.x * 256 + threadIdx.x;
    float m = g_cmax_part[col * 16];
#pragma unroll
    for (int p = 1; p < 16; p++) m = fmaxf(m, g_cmax_part[col * 16 + p]);
    g_cmax[col] = m;
}

// ---------------- att partial via HMMA: U[d][l]=sum_t E[t][d]*V[t][l] --------
// grid (bh=32, split=16); block 256 thr, 8 warps (wd 0..3 x wl 0..1? -> 4x2).
// Warp tile 32(d) x 64(l). E,V tiles 32t x 128 in smem (272B stride).
__global__ void __launch_bounds__(256) att_part_kernel(const float* __restrict__ mask) {
    __shared__ __align__(16) char Eb[32 * EP];
    __shared__ __align__(16) char Vb[32 * EP];
    __shared__ float Ms[128];
    __shared__ float Sred[8][128];
    const int bh = blockIdx.x, sp = blockIdx.y;
    const int b = bh >> 3, h = bh & 7;
    const int tid = threadIdx.x, lane = tid & 31, wid = tid >> 5;
    const int wd = wid & 3, wl = wid >> 2;
    if (tid < 128) Ms[tid] = g_cmax[b * 1024 + h * 128 + tid];
    __syncthreads();

    float acc[2][8][4];
#pragma unroll
    for (int i = 0; i < 2; i++)
#pragma unroll
        for (int j = 0; j < 8; j++)
#pragma unroll
            for (int q = 0; q < 4; q++) acc[i][j][q] = 0.f;
    float ssum[4] = {0.f, 0.f, 0.f, 0.f};

    const uint32_t Ebase = smem_u32(Eb), Vbase = smem_u32(Vb);
    const size_t gbase = ((size_t)b * T_) * D_ + h * 128;
    const int tstart = sp * (T_ / NSPLIT);
    const int dc = (tid & 31) * 4;
    const float m0v = Ms[dc], m1v = Ms[dc + 1], m2v = Ms[dc + 2], m3v = Ms[dc + 3];

    for (int t0 = tstart; t0 < tstart + T_ / NSPLIT; t0 += 32) {
        int myvalid = 0;
#pragma unroll
        for (int s = 0; s < 4; s++) {
            const int tr = (tid >> 5) + s * 8;
            const float mk = mask[b * T_ + t0 + tr];
            uint2 pe = {0u, 0u}, pv = {0u, 0u};
            if (mk != 0.f) {
                myvalid = 1;
                const size_t off = gbase + (size_t)(t0 + tr) * D_ + dc;
                const float4 kv = *(const float4*)(g_k + off);
                const float4 vv = *(const float4*)(g_v + off);
                const float e0 = __expf(kv.x - m0v);
                const float e1 = __expf(kv.y - m1v);
                const float e2 = __expf(kv.z - m2v);
                const float e3 = __expf(kv.w - m3v);
                ssum[0] += e0; ssum[1] += e1; ssum[2] += e2; ssum[3] += e3;
                __nv_bfloat162 e01 = __floats2bfloat162_rn(e0, e1);
                __nv_bfloat162 e23 = __floats2bfloat162_rn(e2, e3);
                __nv_bfloat162 v01 = __floats2bfloat162_rn(vv.x, vv.y);
                __nv_bfloat162 v23 = __floats2bfloat162_rn(vv.z, vv.w);
                pe.x = *(uint32_t*)&e01; pe.y = *(uint32_t*)&e23;
                pv.x = *(uint32_t*)&v01; pv.y = *(uint32_t*)&v23;
            }
            *(uint2*)(Eb + tr * EP + dc * 2) = pe;
            *(uint2*)(Vb + tr * EP + dc * 2) = pv;
        }
        const int anyvalid = __syncthreads_or(myvalid);
        if (anyvalid) {
#pragma unroll
            for (int ks = 0; ks < 2; ks++) {
                uint32_t a[2][4], bf[4][4];
#pragma unroll
                for (int mi = 0; mi < 2; mi++) {
                    const uint32_t ao = (uint32_t)((ks * 16 + ((lane & 16) ? 8 : 0)
                                       + (lane & 7)) * EP
                                       + (wd * 32 + mi * 16) * 2
                                       + ((lane & 8) ? 16 : 0));
                    ldsm_x4t(a[mi], Ebase + ao);
                }
#pragma unroll
                for (int nb = 0; nb < 4; nb++) {
                    const uint32_t bo = (uint32_t)((ks * 16 + ((lane & 8) ? 8 : 0)
                                       + (lane & 7)) * EP
                                       + (wl * 64 + nb * 16) * 2
                                       + ((lane & 16) ? 16 : 0));
                    ldsm_x4t(bf[nb], Vbase + bo);
                }
#pragma unroll
                for (int mi = 0; mi < 2; mi++)
#pragma unroll
                    for (int nb = 0; nb < 4; nb++)
#pragma unroll
                        for (int ns = 0; ns < 2; ns++)
                            mma16816(acc[mi][nb * 2 + ns], a[mi], &bf[nb][ns * 2]);
            }
        }
        __syncthreads();
    }

    // U partials
    const size_t obase = ((size_t)sp * 32 + bh) * 16384;
#pragma unroll
    for (int mi = 0; mi < 2; mi++) {
        const int d0 = wd * 32 + mi * 16 + (lane >> 2);
#pragma unroll
        for (int ni = 0; ni < 8; ni++) {
            const int l0 = wl * 64 + ni * 8 + (lane & 3) * 2;
            *(float2*)(g_attp + obase + (size_t)d0 * 128 + l0) =
                make_float2(acc[mi][ni][0], acc[mi][ni][1]);
            *(float2*)(g_attp + obase + (size_t)(d0 + 8) * 128 + l0) =
                make_float2(acc[mi][ni][2], acc[mi][ni][3]);
        }
    }
    // S reduce: thread (wid, dc) covered t rows {wid, wid+8, wid+16, wid+24}
#pragma unroll
    for (int j = 0; j < 4; j++) Sred[wid][dc + j] = ssum[j];
    __syncthreads();
    if (tid < 128) {
        float s = 0.f;
#pragma unroll
        for (int r = 0; r < 8; r++) s += Sred[r][tid];
        g_Sp[(size_t)sp * 4096 + bh * 128 + tid] = s;
    }
}

// ---------------- att reduce: sum partials, normalize, emit bf16 -------------
__global__ void __launch_bounds__(256) att_reduce_kernel() {
    __shared__ float Ss[128];
    const int bh = blockIdx.x;
    const int tid = threadIdx.x;
    if (tid < 128) {
        float s = 0.f;
#pragma unroll
        for (int p = 0; p < NSPLIT; p++) s += g_Sp[(size_t)p * 4096 + bh * 128 + tid];
        Ss[tid] = 1.0f / s;
    }
    __syncthreads();
    for (int e = tid; e < 16384; e += 256) {
        const int d = e >> 7;
        float s = 0.f;
#pragma unroll
        for (int p = 0; p < NSPLIT; p++) s += g_attp[((size_t)p * 32 + bh) * 16384 + e];
        g_attb[(size_t)bh * 16384 + e] = __float2bfloat16_rn(s * Ss[d]);
    }
}

// ---------------- y = q_sm @ att via HMMA, out = x + y -----------------------
// grid (mt=32, bh=32); block 256 thr; warp (wm 0..3, wl 0..1) tile 32t x 64l.
#define YG_SMEM (2 * 128 * EP + 256)
__global__ void __launch_bounds__(256) ygemm_kernel(const float* __restrict__ x,
                                                    float* __restrict__ out) {
    extern __shared__ char ydsm[];
    const uint32_t qs = (smem_u32(ydsm) + 15) & ~15u;
    const uint32_t as = qs + 128 * EP;
    const int bh = blockIdx.y, mt = blockIdx.x;
    const int b = bh >> 3, h = bh & 7;
    const int tid = threadIdx.x, lane = tid & 31, wid = tid >> 5;
    const int wm = wid & 3, wl = wid >> 2;

    // load q tile (128 x 128 bf16) and att (128 x 128 bf16)
    const size_t qgbase = ((size_t)b * T_ + mt * 128) * D_ + h * 128;
    const size_t agbase = (size_t)bh * 16384;
#pragma unroll
    for (int p = 0; p < 8; p++) {
        const int idx = p * 256 + tid;                 // 0..2047
        const int r = idx >> 4, c8 = idx & 15;
        cp16(qs + r * EP + c8 * 16, g_qb + qgbase + (size_t)r * 1024 + c8 * 8);
        cp16(as + r * EP + c8 * 16, g_attb + agbase + (size_t)r * 128 + c8 * 8);
    }
    CP_COMMIT();
    CP_WAIT(0);
    __syncthreads();

    float acc[2][8][4];
#pragma unroll
    for (int i = 0; i < 2; i++)
#pragma unroll
        for (int j = 0; j < 8; j++)
#pragma unroll
            for (int q = 0; q < 4; q++) acc[i][j][q] = 0.f;

#pragma unroll
    for (int ks = 0; ks < 8; ks++) {
        uint32_t a[2][4], bf[4][4];
#pragma unroll
        for (int mi = 0; mi < 2; mi++) {
            const uint32_t ao = (uint32_t)((wm * 32 + mi * 16 + (lane & 15)) * EP
                               + ks * 32 + ((lane & 16) ? 16 : 0));
            ldsm_x4(a[mi], qs + ao);
        }
#pragma unroll
        for (int nb = 0; nb < 4; nb++) {
            const uint32_t bo = (uint32_t)((ks * 16 + ((lane & 8) ? 8 : 0)
                               + (lane & 7)) * EP
                               + (wl * 64 + nb * 16) * 2
                               + ((lane & 16) ? 16 : 0));
            ldsm_x4t(bf[nb], as + bo);
        }
#pragma unroll
        for (int mi = 0; mi < 2; mi++)
#pragma unroll
            for (int nb = 0; nb < 4; nb++)
#pragma unroll
                for (int ns = 0; ns < 2; ns++)
                    mma16816(acc[mi][nb * 2 + ns], a[mi], &bf[nb][ns * 2]);
    }

    // epilogue: out = x + y
#pragma unroll
    for (int mi = 0; mi < 2; mi++) {
        const size_t row0 = (size_t)b * T_ + mt * 128 + wm * 32 + mi * 16 + (lane >> 2);
        const size_t row1 = row0 + 8;
#pragma unroll
        for (int ni = 0; ni < 8; ni++) {
            const int c = h * 128 + wl * 64 + ni * 8 + (lane & 3) * 2;
            const float2 x0 = *(const float2*)(x + row0 * 1024 + c);
            const float2 x1 = *(const float2*)(x + row1 * 1024 + c);
            float2 o0, o1;
            o0.x = acc[mi][ni][0] + x0.x; o0.y = acc[mi][ni][1] + x0.y;
            o1.x = acc[mi][ni][2] + x1.x; o1.y = acc[mi][ni][3] + x1.y;
            *(float2*)(out + row0 * 1024 + c) = o0;
            *(float2*)(out + row1 * 1024 + c) = o1;
        }
    }
}

// ---------------- launcher ---------------------------------------------------
extern "C" void kernel_launch(void* const* d_in, const int* in_sizes, int n_in,
                              void* d_out, int out_size) {
    const float* x     = (const float*)d_in[0];
    const float* mask  = (const float*)d_in[1];
    const float* Wq    = (const float*)d_in[2];
    const float* bq    = (const float*)d_in[3];
    const float* Wk    = (const float*)d_in[4];
    const float* bk    = (const float*)d_in[5];
    const float* Wv    = (const float*)d_in[6];
    const float* bv    = (const float*)d_in[7];
    const float* gamma = (const float*)d_in[8];
    const float* beta  = (const float*)d_in[9];
    float* out = (float*)d_out;

    static int smem_set = 0;
    if (!smem_set) {
        cudaFuncSetAttribute(qkv_mma, cudaFuncAttributeMaxDynamicSharedMemorySize,
                             QK_SMEM);
        cudaFuncSetAttribute(ygemm_kernel,
                             cudaFuncAttributeMaxDynamicSharedMemorySize, YG_SMEM);
        smem_set = 1;
    }

    ln_kernel<<<NTOK, 256>>>(x, gamma, beta);
    wsplit_kernel<<<dim3(32, 32, 3), 256>>>(Wq, Wk, Wv);

    qkv_mma<<<dim3(4, 128, 3), 512, QK_SMEM>>>(bq, bk, bv, mask);

    qsoftmax_kernel<<<NTOK * H_ / 8, 256>>>();

    kmax_part_kernel<<<dim3(16, 16), 256>>>();
    kmax_final_kernel<<<16, 256>>>();

    att_part_kernel<<<dim3(32, NSPLIT), 256>>>(mask);
    att_reduce_kernel<<<32, 256>>>();

    ygemm_kernel<<<dim3(32, 32), 256, YG_SMEM>>>(x, out);
}

// round 6
// speedup vs baseline: 4.9141x; 1.0520x over previous
#include <cuda_runtime.h>
#include <cuda_bf16.h>
#include <stdint.h>
#include <math.h>

#define B_ 4
#define T_ 4096
#define D_ 1024
#define H_ 8
#define DH_ 128
#define NTOK (B_ * T_)          // 16384
#define NEGV (-1000000.0f)
#define NSPLIT 16
#define EP 272                  // padded smem row stride (bytes) for 128 bf16

// ---------------- scratch (device globals; no allocations allowed) ----------
__device__ __nv_bfloat16 g_xnh[(size_t)NTOK * D_];     // 32 MB xn (bf16)
__device__ __nv_bfloat16 g_wth[(size_t)3 * D_ * D_];   // 6 MB  W^T (q,k,v) bf16
__device__ __nv_bfloat16 g_qb[(size_t)NTOK * D_];      // 32 MB q softmaxed bf16
__device__ __nv_bfloat16 g_kb[(size_t)NTOK * D_];      // 32 MB k (masked) bf16
__device__ __nv_bfloat16 g_vb[(size_t)NTOK * D_];      // 32 MB v (masked) bf16
__device__ float g_cmax_part[B_ * D_ * 16];
__device__ float g_cmax[B_ * D_];
__device__ float g_attp[(size_t)NSPLIT * B_ * H_ * DH_ * DH_];  // 32 MB
__device__ float g_Sp[(size_t)NSPLIT * B_ * D_];
__device__ __nv_bfloat16 g_attb[(size_t)B_ * H_ * DH_ * DH_];   // 1 MB

// ======================= PTX helpers (sm_103 baseline ISA only) ==============
__device__ __forceinline__ uint32_t smem_u32(const void* p) {
    uint32_t a;
    asm("{ .reg .u64 t; cvta.to.shared.u64 t, %1; cvt.u32.u64 %0, t; }"
        : "=r"(a) : "l"(p));
    return a;
}
__device__ __forceinline__ void cp16(uint32_t d, const void* g) {
    asm volatile("cp.async.cg.shared.global [%0], [%1], 16;" :: "r"(d), "l"(g));
}
#define CP_COMMIT()  asm volatile("cp.async.commit_group;")
#define CP_WAIT(n)   asm volatile("cp.async.wait_group %0;" :: "n"(n) : "memory")
#define SW128(o) ((uint32_t)(o) ^ ((((uint32_t)(o)) >> 3) & 0x70))

__device__ __forceinline__ void ldsm_x4(uint32_t* r, uint32_t a) {
    asm volatile("ldmatrix.sync.aligned.m8n8.x4.shared.b16 {%0,%1,%2,%3}, [%4];"
                 : "=r"(r[0]), "=r"(r[1]), "=r"(r[2]), "=r"(r[3]) : "r"(a));
}
__device__ __forceinline__ void ldsm_x4t(uint32_t* r, uint32_t a) {
    asm volatile("ldmatrix.sync.aligned.m8n8.x4.trans.shared.b16 {%0,%1,%2,%3}, [%4];"
                 : "=r"(r[0]), "=r"(r[1]), "=r"(r[2]), "=r"(r[3]) : "r"(a));
}
__device__ __forceinline__ void mma16816(float* d, const uint32_t* a,
                                         const uint32_t* b) {
    asm volatile("mma.sync.aligned.m16n8k16.row.col.f32.bf16.bf16.f32 "
                 "{%0,%1,%2,%3}, {%4,%5,%6,%7}, {%8,%9}, {%0,%1,%2,%3};"
                 : "+f"(d[0]), "+f"(d[1]), "+f"(d[2]), "+f"(d[3])
                 : "r"(a[0]), "r"(a[1]), "r"(a[2]), "r"(a[3]),
                   "r"(b[0]), "r"(b[1]));
}
__device__ __forceinline__ uint32_t pack_bf16(float a, float b) {
    __nv_bfloat162 p = __floats2bfloat162_rn(a, b);
    return *(uint32_t*)&p;
}

// ---------------- LayerNorm: one block per token; emits bf16 ----------------
__global__ void __launch_bounds__(256) ln_kernel(const float* __restrict__ x,
                                                 const float* __restrict__ gamma,
                                                 const float* __restrict__ beta) {
    __shared__ float red[16];
    const int row = blockIdx.x;
    const int tid = threadIdx.x;
    const float4 v = ((const float4*)(x + (size_t)row * D_))[tid];
    float s  = v.x + v.y + v.z + v.w;
    float ss = v.x * v.x + v.y * v.y + v.z * v.z + v.w * v.w;
#pragma unroll
    for (int o = 16; o > 0; o >>= 1) {
        s  += __shfl_xor_sync(0xffffffffu, s, o);
        ss += __shfl_xor_sync(0xffffffffu, ss, o);
    }
    const int warp = tid >> 5, lane = tid & 31;
    if (lane == 0) { red[warp] = s; red[warp + 8] = ss; }
    __syncthreads();
    if (tid < 32) {
        float a = (tid < 8) ? red[tid] : 0.f;
        float b = (tid < 8) ? red[tid + 8] : 0.f;
#pragma unroll
        for (int o = 4; o > 0; o >>= 1) {
            a += __shfl_xor_sync(0xffffffffu, a, o);
            b += __shfl_xor_sync(0xffffffffu, b, o);
        }
        if (tid == 0) { red[0] = a; red[1] = b; }
    }
    __syncthreads();
    const float mu   = red[0] * (1.0f / D_);
    const float var  = red[1] * (1.0f / D_) - mu * mu;
    const float rstd = rsqrtf(var + 1e-5f);
    const float4 g  = ((const float4*)gamma)[tid];
    const float4 bb = ((const float4*)beta)[tid];
    const float o0 = (v.x - mu) * rstd * g.x + bb.x;
    const float o1 = (v.y - mu) * rstd * g.y + bb.y;
    const float o2 = (v.z - mu) * rstd * g.z + bb.z;
    const float o3 = (v.w - mu) * rstd * g.w + bb.w;
    const size_t off = (size_t)row * D_ + tid * 4;
    *(__nv_bfloat162*)(g_xnh + off)     = __floats2bfloat162_rn(o0, o1);
    *(__nv_bfloat162*)(g_xnh + off + 2) = __floats2bfloat162_rn(o2, o3);
}

// ---------------- W transpose to bf16: Wt[n][k] = W[k][n] --------------------
__global__ void __launch_bounds__(256) wsplit_kernel(const float* __restrict__ Wq,
                                                     const float* __restrict__ Wk,
                                                     const float* __restrict__ Wv) {
    __shared__ float t[32][33];
    const float* W = (blockIdx.z == 0) ? Wq : (blockIdx.z == 1) ? Wk : Wv;
    __nv_bfloat16* oh = g_wth + ((size_t)blockIdx.z << 20);
    const int tid = threadIdx.x;
    const int tx = tid & 31, ty = tid >> 5;
    const int bn = blockIdx.x * 32, bk = blockIdx.y * 32;
#pragma unroll
    for (int r = ty; r < 32; r += 8)
        t[r][tx] = W[(size_t)(bk + r) * 1024 + bn + tx];
    __syncthreads();
#pragma unroll
    for (int r = ty; r < 32; r += 8)
        oh[(size_t)(bn + r) * 1024 + bk + tx] = __float2bfloat16_rn(t[tx][r]);
}

// ---------------- QKV GEMM via mma.sync bf16 + fused epilogues ---------------
// Tile 128(M) x 256(N), BK=64, 3-stage cp.async, 512 threads.
// 16 warps: warp (wm 0..3, wn 0..3) owns 32x64.
// mode 0: q -> +bias -> softmax over each 128-col head -> bf16 g_qb
// mode 1: k -> +bias+(1-m)*NEG -> bf16 g_kb
// mode 2: v -> (+bias)*m -> bf16 g_vb
#define OFF_A  0
#define OFF_B  16384
#define STG    49152
#define QK_SMEM (3 * STG + 1024)

__global__ void __launch_bounds__(512, 1)
qkv_mma(const float* __restrict__ bq, const float* __restrict__ bk_,
        const float* __restrict__ bv, const float* __restrict__ mask) {
    extern __shared__ char dsm[];
    const uint32_t base = (smem_u32(dsm) + 1023) & ~1023u;
    const int tid = threadIdx.x, lane = tid & 31, wid = tid >> 5;
    const int wm = wid & 3, wn = wid >> 2;
    const int mode = blockIdx.z;
    const int n0 = blockIdx.x * 256;
    const size_t m0 = (size_t)blockIdx.y * 128;

    const __nv_bfloat16* A = g_xnh;
    const __nv_bfloat16* Bw = g_wth + ((size_t)mode << 20);

    float acc[2][8][4];
#pragma unroll
    for (int i = 0; i < 2; i++)
#pragma unroll
        for (int j = 0; j < 8; j++)
#pragma unroll
            for (int q = 0; q < 4; q++) acc[i][j][q] = 0.f;

    auto issue = [&](int i) {
        const int k0 = i * 64;
        const uint32_t sb = base + (i % 3) * STG;
#pragma unroll
        for (int p = 0; p < 2; p++) {
            const int idx = p * 512 + tid;             // 0..1023
            const int r = idx >> 3, kc = idx & 7;
            const uint32_t sw = SW128(r * 128 + kc * 16);
            cp16(sb + OFF_A + sw, A + (m0 + r) * 1024 + k0 + kc * 8);
        }
#pragma unroll
        for (int p = 0; p < 4; p++) {
            const int idx = p * 512 + tid;             // 0..2047
            const int r = idx >> 3, kc = idx & 7;
            const uint32_t sw = SW128(r * 128 + kc * 16);
            cp16(sb + OFF_B + sw, Bw + (size_t)(n0 + r) * 1024 + k0 + kc * 8);
        }
        CP_COMMIT();
    };

    issue(0); issue(1);
    const int arow  = wm * 32 + (lane & 15);
    const int acolb = (lane >> 4) * 16;
    const int brow  = wn * 64 + (lane & 7) + ((lane & 16) ? 8 : 0);
    const int bcolb = (lane & 8) ? 16 : 0;

    for (int i = 0; i < 16; i++) {
        if (i + 2 < 16)      { issue(i + 2); CP_WAIT(2); }
        else if (i + 1 < 16) { CP_WAIT(1); }
        else                 { CP_WAIT(0); }
        __syncthreads();
        const uint32_t sb = base + (i % 3) * STG;

#pragma unroll
        for (int ks = 0; ks < 4; ks++) {
            const int kb = ks * 32;
            uint32_t ah[2][4];
#pragma unroll
            for (int mi = 0; mi < 2; mi++) {
                const uint32_t ao = SW128((arow + mi * 16) * 128 + kb + acolb);
                ldsm_x4(ah[mi], sb + OFF_A + ao);
            }
#pragma unroll
            for (int nb = 0; nb < 4; nb++) {
                const uint32_t bo = SW128((brow + nb * 16) * 128 + kb + bcolb);
                uint32_t bh[4];
                ldsm_x4(bh, sb + OFF_B + bo);
#pragma unroll
                for (int mi = 0; mi < 2; mi++)
#pragma unroll
                    for (int ns = 0; ns < 2; ns++)
                        mma16816(acc[mi][nb * 2 + ns], ah[mi], &bh[ns * 2]);
            }
        }
        __syncthreads();
    }

    const int rl0 = wm * 32 + (lane >> 2);            // local row (0..127)
    const int cl0 = wn * 64 + (lane & 3) * 2;         // local col (0..255)

    if (mode == 0) {
        // ---- fused q softmax: stage fp32 to smem, per-row-head softmax ----
        float* S = (float*)dsm;                        // 128 x 256 fp32 (128KB)
#pragma unroll
        for (int mi = 0; mi < 2; mi++) {
            const int r0 = rl0 + mi * 16;
#pragma unroll
            for (int ni = 0; ni < 8; ni++) {
                const int c = cl0 + ni * 8;
                *(float2*)&S[(r0)     * 256 + c] = make_float2(acc[mi][ni][0], acc[mi][ni][1]);
                *(float2*)&S[(r0 + 8) * 256 + c] = make_float2(acc[mi][ni][2], acc[mi][ni][3]);
            }
        }
        __syncthreads();
        // 256 row-head units; each warp handles 16
        const float4 bqv = *(const float4*)(bq + n0 + (tid & 32) * 4 + lane * 4);
        // (note: seg depends on unit parity; reload bias inside loop instead)
        (void)bqv;
#pragma unroll
        for (int u = wid * 16; u < wid * 16 + 16; u++) {
            const int row = u >> 1, seg = u & 1;
            const float4 bias4 = *(const float4*)(bq + n0 + seg * 128 + lane * 4);
            float4 v = *(const float4*)&S[row * 256 + seg * 128 + lane * 4];
            v.x += bias4.x; v.y += bias4.y; v.z += bias4.z; v.w += bias4.w;
            float mx = fmaxf(fmaxf(v.x, v.y), fmaxf(v.z, v.w));
#pragma unroll
            for (int o = 16; o > 0; o >>= 1)
                mx = fmaxf(mx, __shfl_xor_sync(0xffffffffu, mx, o));
            v.x = __expf(v.x - mx); v.y = __expf(v.y - mx);
            v.z = __expf(v.z - mx); v.w = __expf(v.w - mx);
            float sm = v.x + v.y + v.z + v.w;
#pragma unroll
            for (int o = 16; o > 0; o >>= 1)
                sm += __shfl_xor_sync(0xffffffffu, sm, o);
            const float inv = 1.0f / sm;
            uint2 pk;
            pk.x = pack_bf16(v.x * inv, v.y * inv);
            pk.y = pack_bf16(v.z * inv, v.w * inv);
            *(uint2*)(g_qb + (m0 + row) * 1024 + n0 + seg * 128 + lane * 4) = pk;
        }
    } else {
        const float* bias = (mode == 1) ? bk_ : bv;
        __nv_bfloat16* __restrict__ C = (mode == 1) ? g_kb : g_vb;
#pragma unroll
        for (int mi = 0; mi < 2; mi++) {
            const int r0 = (int)m0 + rl0 + mi * 16;
            const int r1 = r0 + 8;
            const float mk0 = mask[r0], mk1 = mask[r1];
            const float ma0 = (mode == 1) ? (1.0f - mk0) * NEGV : 0.f;
            const float ma1 = (mode == 1) ? (1.0f - mk1) * NEGV : 0.f;
            const float mm0 = (mode == 2) ? mk0 : 1.f;
            const float mm1 = (mode == 2) ? mk1 : 1.f;
#pragma unroll
            for (int ni = 0; ni < 8; ni++) {
                const int c = n0 + cl0 + ni * 8;
                const float b0 = bias[c], b1 = bias[c + 1];
                *(uint32_t*)(C + (size_t)r0 * 1024 + c) =
                    pack_bf16((acc[mi][ni][0] + b0 + ma0) * mm0,
                              (acc[mi][ni][1] + b1 + ma0) * mm0);
                *(uint32_t*)(C + (size_t)r1 * 1024 + c) =
                    pack_bf16((acc[mi][ni][2] + b0 + ma1) * mm1,
                              (acc[mi][ni][3] + b1 + ma1) * mm1);
            }
        }
    }
}

// ---------------- k column max over time (2-pass, bf16 input) ----------------
__global__ void __launch_bounds__(256) kmax_part_kernel() {
    const int col = blockIdx.x * 256 + threadIdx.x;
    const int b = col >> 10, d = col & 1023;
    const __nv_bfloat16* base = g_kb + ((size_t)b * T_) * D_ + d;
    const int t0 = blockIdx.y * 256;
    float m = -3.4e38f;
#pragma unroll 8
    for (int t = 0; t < 256; t++)
        m = fmaxf(m, __bfloat162float(base[(size_t)(t0 + t) * D_]));
    g_cmax_part[col * 16 + blockIdx.y] = m;
}

__global__ void __launch_bounds__(256) kmax_final_kernel() {
    const int col = blockIdx.x * 256 + threadIdx.x;
    float m = g_cmax_part[col * 16];
#pragma unroll
    for (int p = 1; p < 16; p++) m = fmaxf(m, g_cmax_part[col * 16 + p]);
    g_cmax[col] = m;
}

// ---------------- att partial via HMMA: U[d][l]=sum_t E[t][d]*V[t][l] --------
// grid (bh=32, split=16); block 256 thr, 8 warps (wd 0..3 x wl 0..1).
// E computed from bf16 k; V cp.async'd directly (already mask-zeroed bf16).
__global__ void __launch_bounds__(256) att_part_kernel(const float* __restrict__ mask) {
    __shared__ __align__(16) char Eb[32 * EP];
    __shared__ __align__(16) char Vb[32 * EP];
    __shared__ float Ms[128];
    __shared__ float Sred[8][128];
    const int bh = blockIdx.x, sp = blockIdx.y;
    const int b = bh >> 3, h = bh & 7;
    const int tid = threadIdx.x, lane = tid & 31, wid = tid >> 5;
    const int wd = wid & 3, wl = wid >> 2;
    if (tid < 128) Ms[tid] = g_cmax[b * 1024 + h * 128 + tid];
    __syncthreads();

    float acc[2][8][4];
#pragma unroll
    for (int i = 0; i < 2; i++)
#pragma unroll
        for (int j = 0; j < 8; j++)
#pragma unroll
            for (int q = 0; q < 4; q++) acc[i][j][q] = 0.f;
    float ssum[4] = {0.f, 0.f, 0.f, 0.f};

    const uint32_t Ebase = smem_u32(Eb), Vbase = smem_u32(Vb);
    const size_t gbase = ((size_t)b * T_) * D_ + h * 128;
    const int tstart = sp * (T_ / NSPLIT);
    const int dc = (tid & 31) * 4;
    const float m0v = Ms[dc], m1v = Ms[dc + 1], m2v = Ms[dc + 2], m3v = Ms[dc + 3];

    for (int t0 = tstart; t0 < tstart + T_ / NSPLIT; t0 += 32) {
        // V tile: direct cp.async of bf16 (masked rows already zero)
#pragma unroll
        for (int it = 0; it < 2; it++) {
            const int idx = it * 256 + tid;            // 0..511
            const int tr = idx >> 4, ch = idx & 15;
            cp16(Vbase + tr * EP + ch * 16,
                 g_vb + gbase + (size_t)(t0 + tr) * D_ + ch * 8);
        }
        CP_COMMIT();
        // E tile: exp(k - M) from bf16 k
        int myvalid = 0;
#pragma unroll
        for (int s = 0; s < 4; s++) {
            const int tr = (tid >> 5) + s * 8;
            const float mk = mask[b * T_ + t0 + tr];
            uint2 pe = {0u, 0u};
            if (mk != 0.f) {
                myvalid = 1;
                const uint2 kp = *(const uint2*)(g_kb + gbase + (size_t)(t0 + tr) * D_ + dc);
                const __nv_bfloat162 k01 = *(const __nv_bfloat162*)&kp.x;
                const __nv_bfloat162 k23 = *(const __nv_bfloat162*)&kp.y;
                const float e0 = __expf(__bfloat162float(k01.x) - m0v);
                const float e1 = __expf(__bfloat162float(k01.y) - m1v);
                const float e2 = __expf(__bfloat162float(k23.x) - m2v);
                const float e3 = __expf(__bfloat162float(k23.y) - m3v);
                ssum[0] += e0; ssum[1] += e1; ssum[2] += e2; ssum[3] += e3;
                pe.x = pack_bf16(e0, e1);
                pe.y = pack_bf16(e2, e3);
            }
            *(uint2*)(Eb + tr * EP + dc * 2) = pe;
        }
        CP_WAIT(0);
        const int anyvalid = __syncthreads_or(myvalid);
        if (anyvalid) {
#pragma unroll
            for (int ks = 0; ks < 2; ks++) {
                uint32_t a[2][4], bf[4][4];
#pragma unroll
                for (int mi = 0; mi < 2; mi++) {
                    const uint32_t ao = (uint32_t)((ks * 16 + ((lane & 16) ? 8 : 0)
                                       + (lane & 7)) * EP
                                       + (wd * 32 + mi * 16) * 2
                                       + ((lane & 8) ? 16 : 0));
                    ldsm_x4t(a[mi], Ebase + ao);
                }
#pragma unroll
                for (int nb = 0; nb < 4; nb++) {
                    const uint32_t bo = (uint32_t)((ks * 16 + ((lane & 8) ? 8 : 0)
                                       + (lane & 7)) * EP
                                       + (wl * 64 + nb * 16) * 2
                                       + ((lane & 16) ? 16 : 0));
                    ldsm_x4t(bf[nb], Vbase + bo);
                }
#pragma unroll
                for (int mi = 0; mi < 2; mi++)
#pragma unroll
                    for (int nb = 0; nb < 4; nb++)
#pragma unroll
                        for (int ns = 0; ns < 2; ns++)
                            mma16816(acc[mi][nb * 2 + ns], a[mi], &bf[nb][ns * 2]);
            }
        }
        __syncthreads();
    }

    // U partials
    const size_t obase = ((size_t)sp * 32 + bh) * 16384;
#pragma unroll
    for (int mi = 0; mi < 2; mi++) {
        const int d0 = wd * 32 + mi * 16 + (lane >> 2);
#pragma unroll
        for (int ni = 0; ni < 8; ni++) {
            const int l0 = wl * 64 + ni * 8 + (lane & 3) * 2;
            *(float2*)(g_attp + obase + (size_t)d0 * 128 + l0) =
                make_float2(acc[mi][ni][0], acc[mi][ni][1]);
            *(float2*)(g_attp + obase + (size_t)(d0 + 8) * 128 + l0) =
                make_float2(acc[mi][ni][2], acc[mi][ni][3]);
        }
    }
#pragma unroll
    for (int j = 0; j < 4; j++) Sred[wid][dc + j] = ssum[j];
    __syncthreads();
    if (tid < 128) {
        float s = 0.f;
#pragma unroll
        for (int r = 0; r < 8; r++) s += Sred[r][tid];
        g_Sp[(size_t)sp * 4096 + bh * 128 + tid] = s;
    }
}

// ---------------- att reduce: sum partials, normalize, emit bf16 -------------
__global__ void __launch_bounds__(256) att_reduce_kernel() {
    __shared__ float Ss[128];
    const int bh = blockIdx.x;
    const int tid = threadIdx.x;
    if (tid < 128) {
        float s = 0.f;
#pragma unroll
        for (int p = 0; p < NSPLIT; p++) s += g_Sp[(size_t)p * 4096 + bh * 128 + tid];
        Ss[tid] = 1.0f / s;
    }
    __syncthreads();
    for (int e = tid; e < 16384; e += 256) {
        const int d = e >> 7;
        float s = 0.f;
#pragma unroll
        for (int p = 0; p < NSPLIT; p++) s += g_attp[((size_t)p * 32 + bh) * 16384 + e];
        g_attb[(size_t)bh * 16384 + e] = __float2bfloat16_rn(s * Ss[d]);
    }
}

// ---------------- y = q_sm @ att via HMMA, out = x + y -----------------------
#define YG_SMEM (2 * 128 * EP + 256)
__global__ void __launch_bounds__(256) ygemm_kernel(const float* __restrict__ x,
                                                    float* __restrict__ out) {
    extern __shared__ char ydsm[];
    const uint32_t qs = (smem_u32(ydsm) + 15) & ~15u;
    const uint32_t as = qs + 128 * EP;
    const int bh = blockIdx.y, mt = blockIdx.x;
    const int b = bh >> 3, h = bh & 7;
    const int tid = threadIdx.x, lane = tid & 31, wid = tid >> 5;
    const int wm = wid & 3, wl = wid >> 2;

    const size_t qgbase = ((size_t)b * T_ + mt * 128) * D_ + h * 128;
    const size_t agbase = (size_t)bh * 16384;
#pragma unroll
    for (int p = 0; p < 8; p++) {
        const int idx = p * 256 + tid;                 // 0..2047
        const int r = idx >> 4, c8 = idx & 15;
        cp16(qs + r * EP + c8 * 16, g_qb + qgbase + (size_t)r * 1024 + c8 * 8);
        cp16(as + r * EP + c8 * 16, g_attb + agbase + (size_t)r * 128 + c8 * 8);
    }
    CP_COMMIT();
    CP_WAIT(0);
    __syncthreads();

    float acc[2][8][4];
#pragma unroll
    for (int i = 0; i < 2; i++)
#pragma unroll
        for (int j = 0; j < 8; j++)
#pragma unroll
            for (int q = 0; q < 4; q++) acc[i][j][q] = 0.f;

#pragma unroll
    for (int ks = 0; ks < 8; ks++) {
        uint32_t a[2][4], bf[4][4];
#pragma unroll
        for (int mi = 0; mi < 2; mi++) {
            const uint32_t ao = (uint32_t)((wm * 32 + mi * 16 + (lane & 15)) * EP
                               + ks * 32 + ((lane & 16) ? 16 : 0));
            ldsm_x4(a[mi], qs + ao);
        }
#pragma unroll
        for (int nb = 0; nb < 4; nb++) {
            const uint32_t bo = (uint32_t)((ks * 16 + ((lane & 8) ? 8 : 0)
                               + (lane & 7)) * EP
                               + (wl * 64 + nb * 16) * 2
                               + ((lane & 16) ? 16 : 0));
            ldsm_x4t(bf[nb], as + bo);
        }
#pragma unroll
        for (int mi = 0; mi < 2; mi++)
#pragma unroll
            for (int nb = 0; nb < 4; nb++)
#pragma unroll
                for (int ns = 0; ns < 2; ns++)
                    mma16816(acc[mi][nb * 2 + ns], a[mi], &bf[nb][ns * 2]);
    }

#pragma unroll
    for (int mi = 0; mi < 2; mi++) {
        const size_t row0 = (size_t)b * T_ + mt * 128 + wm * 32 + mi * 16 + (lane >> 2);
        const size_t row1 = row0 + 8;
#pragma unroll
        for (int ni = 0; ni < 8; ni++) {
            const int c = h * 128 + wl * 64 + ni * 8 + (lane & 3) * 2;
            const float2 x0 = *(const float2*)(x + row0 * 1024 + c);
            const float2 x1 = *(const float2*)(x + row1 * 1024 + c);
            float2 o0, o1;
            o0.x = acc[mi][ni][0] + x0.x; o0.y = acc[mi][ni][1] + x0.y;
            o1.x = acc[mi][ni][2] + x1.x; o1.y = acc[mi][ni][3] + x1.y;
            *(float2*)(out + row0 * 1024 + c) = o0;
            *(float2*)(out + row1 * 1024 + c) = o1;
        }
    }
}

// ---------------- launcher ---------------------------------------------------
extern "C" void kernel_launch(void* const* d_in, const int* in_sizes, int n_in,
                              void* d_out, int out_size) {
    const float* x     = (const float*)d_in[0];
    const float* mask  = (const float*)d_in[1];
    const float* Wq    = (const float*)d_in[2];
    const float* bq    = (const float*)d_in[3];
    const float* Wk    = (const float*)d_in[4];
    const float* bk    = (const float*)d_in[5];
    const float* Wv    = (const float*)d_in[6];
    const float* bv    = (const float*)d_in[7];
    const float* gamma = (const float*)d_in[8];
    const float* beta  = (const float*)d_in[9];
    float* out = (float*)d_out;

    static int smem_set = 0;
    if (!smem_set) {
        cudaFuncSetAttribute(qkv_mma, cudaFuncAttributeMaxDynamicSharedMemorySize,
                             QK_SMEM);
        cudaFuncSetAttribute(ygemm_kernel,
                             cudaFuncAttributeMaxDynamicSharedMemorySize, YG_SMEM);
        smem_set = 1;
    }

    ln_kernel<<<NTOK, 256>>>(x, gamma, beta);
    wsplit_kernel<<<dim3(32, 32, 3), 256>>>(Wq, Wk, Wv);

    qkv_mma<<<dim3(4, 128, 3), 512, QK_SMEM>>>(bq, bk, bv, mask);

    kmax_part_kernel<<<dim3(16, 16), 256>>>();
    kmax_final_kernel<<<16, 256>>>();

    att_part_kernel<<<dim3(32, NSPLIT), 256>>>(mask);
    att_reduce_kernel<<<32, 256>>>();

    ygemm_kernel<<<dim3(32, 32), 256, YG_SMEM>>>(x, out);
}

// round 7
// speedup vs baseline: 5.2905x; 1.0766x over previous
#include <cuda_runtime.h>
#include <cuda_bf16.h>
#include <stdint.h>
#include <math.h>

#define B_ 4
#define T_ 4096
#define D_ 1024
#define H_ 8
#define DH_ 128
#define NTOK (B_ * T_)          // 16384
#define NEGV (-1000000.0f)
#define NSPLIT 16
#define EP 272                  // padded smem row stride (bytes) for 128 bf16
#define KCH 64                  // kmax t-chunks

// ---------------- scratch (device globals; no allocations allowed) ----------
__device__ __nv_bfloat16 g_xnh[(size_t)NTOK * D_];     // 32 MB xn (bf16)
__device__ __nv_bfloat16 g_wth[(size_t)3 * D_ * D_];   // 6 MB  W^T (q,k,v) bf16
__device__ __nv_bfloat16 g_qb[(size_t)NTOK * D_];      // 32 MB q softmaxed bf16
__device__ __nv_bfloat16 g_kb[(size_t)NTOK * D_];      // 32 MB k (masked) bf16
__device__ __nv_bfloat16 g_vb[(size_t)NTOK * D_];      // 32 MB v (masked) bf16
__device__ float g_cmax_part[B_ * D_ * KCH];           // 1 MB
__device__ float g_cmax[B_ * D_];
__device__ float g_attp[(size_t)NSPLIT * B_ * H_ * DH_ * DH_];  // 32 MB
__device__ float g_Sp[(size_t)NSPLIT * B_ * D_];
__device__ __nv_bfloat16 g_attb[(size_t)B_ * H_ * DH_ * DH_];   // 1 MB

// ======================= PTX helpers (sm_103 baseline ISA only) ==============
__device__ __forceinline__ uint32_t smem_u32(const void* p) {
    uint32_t a;
    asm("{ .reg .u64 t; cvta.to.shared.u64 t, %1; cvt.u32.u64 %0, t; }"
        : "=r"(a) : "l"(p));
    return a;
}
__device__ __forceinline__ void cp16(uint32_t d, const void* g) {
    asm volatile("cp.async.cg.shared.global [%0], [%1], 16;" :: "r"(d), "l"(g));
}
#define CP_COMMIT()  asm volatile("cp.async.commit_group;")
#define CP_WAIT(n)   asm volatile("cp.async.wait_group %0;" :: "n"(n) : "memory")
#define SW128(o) ((uint32_t)(o) ^ ((((uint32_t)(o)) >> 3) & 0x70))

__device__ __forceinline__ void ldsm_x4(uint32_t* r, uint32_t a) {
    asm volatile("ldmatrix.sync.aligned.m8n8.x4.shared.b16 {%0,%1,%2,%3}, [%4];"
                 : "=r"(r[0]), "=r"(r[1]), "=r"(r[2]), "=r"(r[3]) : "r"(a));
}
__device__ __forceinline__ void ldsm_x4t(uint32_t* r, uint32_t a) {
    asm volatile("ldmatrix.sync.aligned.m8n8.x4.trans.shared.b16 {%0,%1,%2,%3}, [%4];"
                 : "=r"(r[0]), "=r"(r[1]), "=r"(r[2]), "=r"(r[3]) : "r"(a));
}
__device__ __forceinline__ void mma16816(float* d, const uint32_t* a,
                                         const uint32_t* b) {
    asm volatile("mma.sync.aligned.m16n8k16.row.col.f32.bf16.bf16.f32 "
                 "{%0,%1,%2,%3}, {%4,%5,%6,%7}, {%8,%9}, {%0,%1,%2,%3};"
                 : "+f"(d[0]), "+f"(d[1]), "+f"(d[2]), "+f"(d[3])
                 : "r"(a[0]), "r"(a[1]), "r"(a[2]), "r"(a[3]),
                   "r"(b[0]), "r"(b[1]));
}
__device__ __forceinline__ uint32_t pack_bf16(float a, float b) {
    __nv_bfloat162 p = __floats2bfloat162_rn(a, b);
    return *(uint32_t*)&p;
}

// ---------------- LayerNorm: one block per token; emits bf16 ----------------
__global__ void __launch_bounds__(256) ln_kernel(const float* __restrict__ x,
                                                 const float* __restrict__ gamma,
                                                 const float* __restrict__ beta) {
    __shared__ float red[16];
    const int row = blockIdx.x;
    const int tid = threadIdx.x;
    const float4 v = ((const float4*)(x + (size_t)row * D_))[tid];
    float s  = v.x + v.y + v.z + v.w;
    float ss = v.x * v.x + v.y * v.y + v.z * v.z + v.w * v.w;
#pragma unroll
    for (int o = 16; o > 0; o >>= 1) {
        s  += __shfl_xor_sync(0xffffffffu, s, o);
        ss += __shfl_xor_sync(0xffffffffu, ss, o);
    }
    const int warp = tid >> 5, lane = tid & 31;
    if (lane == 0) { red[warp] = s; red[warp + 8] = ss; }
    __syncthreads();
    if (tid < 32) {
        float a = (tid < 8) ? red[tid] : 0.f;
        float b = (tid < 8) ? red[tid + 8] : 0.f;
#pragma unroll
        for (int o = 4; o > 0; o >>= 1) {
            a += __shfl_xor_sync(0xffffffffu, a, o);
            b += __shfl_xor_sync(0xffffffffu, b, o);
        }
        if (tid == 0) { red[0] = a; red[1] = b; }
    }
    __syncthreads();
    const float mu   = red[0] * (1.0f / D_);
    const float var  = red[1] * (1.0f / D_) - mu * mu;
    const float rstd = rsqrtf(var + 1e-5f);
    const float4 g  = ((const float4*)gamma)[tid];
    const float4 bb = ((const float4*)beta)[tid];
    const float o0 = (v.x - mu) * rstd * g.x + bb.x;
    const float o1 = (v.y - mu) * rstd * g.y + bb.y;
    const float o2 = (v.z - mu) * rstd * g.z + bb.z;
    const float o3 = (v.w - mu) * rstd * g.w + bb.w;
    const size_t off = (size_t)row * D_ + tid * 4;
    *(__nv_bfloat162*)(g_xnh + off)     = __floats2bfloat162_rn(o0, o1);
    *(__nv_bfloat162*)(g_xnh + off + 2) = __floats2bfloat162_rn(o2, o3);
}

// ---------------- W transpose to bf16: Wt[n][k] = W[k][n] --------------------
__global__ void __launch_bounds__(256) wsplit_kernel(const float* __restrict__ Wq,
                                                     const float* __restrict__ Wk,
                                                     const float* __restrict__ Wv) {
    __shared__ float t[32][33];
    const float* W = (blockIdx.z == 0) ? Wq : (blockIdx.z == 1) ? Wk : Wv;
    __nv_bfloat16* oh = g_wth + ((size_t)blockIdx.z << 20);
    const int tid = threadIdx.x;
    const int tx = tid & 31, ty = tid >> 5;
    const int bn = blockIdx.x * 32, bk = blockIdx.y * 32;
#pragma unroll
    for (int r = ty; r < 32; r += 8)
        t[r][tx] = W[(size_t)(bk + r) * 1024 + bn + tx];
    __syncthreads();
#pragma unroll
    for (int r = ty; r < 32; r += 8)
        oh[(size_t)(bn + r) * 1024 + bk + tx] = __float2bfloat16_rn(t[tx][r]);
}

// ---------------- QKV GEMM via mma.sync bf16 + fused epilogues ---------------
// Tile 128(M) x 256(N), BK=64, 3-stage cp.async, 256 threads.
// 8 warps: warp (wm 0..1, wn 0..3) owns 64x64 (less ldsm crossbar traffic).
#define OFF_A  0
#define OFF_B  16384
#define STG    49152
#define QK_SMEM (3 * STG + 1024)

__global__ void __launch_bounds__(256, 1)
qkv_mma(const float* __restrict__ bq, const float* __restrict__ bk_,
        const float* __restrict__ bv, const float* __restrict__ mask) {
    extern __shared__ char dsm[];
    const uint32_t base = (smem_u32(dsm) + 1023) & ~1023u;
    const int tid = threadIdx.x, lane = tid & 31, wid = tid >> 5;
    const int wm = wid & 1, wn = wid >> 1;
    const int mode = blockIdx.z;
    const int n0 = blockIdx.x * 256;
    const size_t m0 = (size_t)blockIdx.y * 128;

    const __nv_bfloat16* A = g_xnh;
    const __nv_bfloat16* Bw = g_wth + ((size_t)mode << 20);

    float acc[4][8][4];
#pragma unroll
    for (int i = 0; i < 4; i++)
#pragma unroll
        for (int j = 0; j < 8; j++)
#pragma unroll
            for (int q = 0; q < 4; q++) acc[i][j][q] = 0.f;

    auto issue = [&](int i) {
        const int k0 = i * 64;
        const uint32_t sb = base + (i % 3) * STG;
#pragma unroll
        for (int p = 0; p < 4; p++) {
            const int idx = p * 256 + tid;             // 0..1023
            const int r = idx >> 3, kc = idx & 7;
            const uint32_t sw = SW128(r * 128 + kc * 16);
            cp16(sb + OFF_A + sw, A + (m0 + r) * 1024 + k0 + kc * 8);
        }
#pragma unroll
        for (int p = 0; p < 8; p++) {
            const int idx = p * 256 + tid;             // 0..2047
            const int r = idx >> 3, kc = idx & 7;
            const uint32_t sw = SW128(r * 128 + kc * 16);
            cp16(sb + OFF_B + sw, Bw + (size_t)(n0 + r) * 1024 + k0 + kc * 8);
        }
        CP_COMMIT();
    };

    issue(0); issue(1);
    const int arow  = wm * 64 + (lane & 15);
    const int acolb = (lane >> 4) * 16;
    const int brow  = wn * 64 + (lane & 7) + ((lane & 16) ? 8 : 0);
    const int bcolb = (lane & 8) ? 16 : 0;

    for (int i = 0; i < 16; i++) {
        if (i + 2 < 16)      { issue(i + 2); CP_WAIT(2); }
        else if (i + 1 < 16) { CP_WAIT(1); }
        else                 { CP_WAIT(0); }
        __syncthreads();
        const uint32_t sb = base + (i % 3) * STG;

#pragma unroll
        for (int ks = 0; ks < 4; ks++) {
            const int kb = ks * 32;
            uint32_t ah[4][4];
#pragma unroll
            for (int mi = 0; mi < 4; mi++) {
                const uint32_t ao = SW128((arow + mi * 16) * 128 + kb + acolb);
                ldsm_x4(ah[mi], sb + OFF_A + ao);
            }
#pragma unroll
            for (int nb = 0; nb < 4; nb++) {
                const uint32_t bo = SW128((brow + nb * 16) * 128 + kb + bcolb);
                uint32_t bh[4];
                ldsm_x4(bh, sb + OFF_B + bo);
#pragma unroll
                for (int mi = 0; mi < 4; mi++)
#pragma unroll
                    for (int ns = 0; ns < 2; ns++)
                        mma16816(acc[mi][nb * 2 + ns], ah[mi], &bh[ns * 2]);
            }
        }
        __syncthreads();
    }

    const int rl0 = wm * 64 + (lane >> 2);            // local row base
    const int cl0 = wn * 64 + (lane & 3) * 2;         // local col base

    if (mode == 0) {
        // ---- fused q softmax: stage fp32 to smem, per-row-head softmax ----
        float* S = (float*)dsm;                        // 128 x 256 fp32 (128KB)
#pragma unroll
        for (int mi = 0; mi < 4; mi++) {
            const int r0 = rl0 + mi * 16;
#pragma unroll
            for (int ni = 0; ni < 8; ni++) {
                const int c = cl0 + ni * 8;
                *(float2*)&S[(r0)     * 256 + c] = make_float2(acc[mi][ni][0], acc[mi][ni][1]);
                *(float2*)&S[(r0 + 8) * 256 + c] = make_float2(acc[mi][ni][2], acc[mi][ni][3]);
            }
        }
        __syncthreads();
        // 256 row-head units; each warp handles 32
#pragma unroll
        for (int u = wid * 32; u < wid * 32 + 32; u++) {
            const int row = u >> 1, seg = u & 1;
            const float4 bias4 = *(const float4*)(bq + n0 + seg * 128 + lane * 4);
            float4 v = *(const float4*)&S[row * 256 + seg * 128 + lane * 4];
            v.x += bias4.x; v.y += bias4.y; v.z += bias4.z; v.w += bias4.w;
            float mx = fmaxf(fmaxf(v.x, v.y), fmaxf(v.z, v.w));
#pragma unroll
            for (int o = 16; o > 0; o >>= 1)
                mx = fmaxf(mx, __shfl_xor_sync(0xffffffffu, mx, o));
            v.x = __expf(v.x - mx); v.y = __expf(v.y - mx);
            v.z = __expf(v.z - mx); v.w = __expf(v.w - mx);
            float sm = v.x + v.y + v.z + v.w;
#pragma unroll
            for (int o = 16; o > 0; o >>= 1)
                sm += __shfl_xor_sync(0xffffffffu, sm, o);
            const float inv = 1.0f / sm;
            uint2 pk;
            pk.x = pack_bf16(v.x * inv, v.y * inv);
            pk.y = pack_bf16(v.z * inv, v.w * inv);
            *(uint2*)(g_qb + (m0 + row) * 1024 + n0 + seg * 128 + lane * 4) = pk;
        }
    } else {
        const float* bias = (mode == 1) ? bk_ : bv;
        __nv_bfloat16* __restrict__ C = (mode == 1) ? g_kb : g_vb;
#pragma unroll
        for (int mi = 0; mi < 4; mi++) {
            const int r0 = (int)m0 + rl0 + mi * 16;
            const int r1 = r0 + 8;
            const float mk0 = mask[r0], mk1 = mask[r1];
            const float ma0 = (mode == 1) ? (1.0f - mk0) * NEGV : 0.f;
            const float ma1 = (mode == 1) ? (1.0f - mk1) * NEGV : 0.f;
            const float mm0 = (mode == 2) ? mk0 : 1.f;
            const float mm1 = (mode == 2) ? mk1 : 1.f;
#pragma unroll
            for (int ni = 0; ni < 8; ni++) {
                const int c = n0 + cl0 + ni * 8;
                const float b0 = bias[c], b1 = bias[c + 1];
                *(uint32_t*)(C + (size_t)r0 * 1024 + c) =
                    pack_bf16((acc[mi][ni][0] + b0 + ma0) * mm0,
                              (acc[mi][ni][1] + b1 + ma0) * mm0);
                *(uint32_t*)(C + (size_t)r1 * 1024 + c) =
                    pack_bf16((acc[mi][ni][2] + b0 + ma1) * mm1,
                              (acc[mi][ni][3] + b1 + ma1) * mm1);
            }
        }
    }
}

// ---------------- k column max over time (2-pass, bf16, vectorized) ----------
// pass 1: grid (2, KCH), block 256; thread handles 8 cols x 64 t rows.
__global__ void __launch_bounds__(256) kmax_part_kernel() {
    const int cg = blockIdx.x * 256 + threadIdx.x;     // 0..511 col-group of 8
    const int col0 = cg * 8;
    const int b = col0 >> 10, d = col0 & 1023;
    const __nv_bfloat16* base = g_kb + ((size_t)b * T_) * D_ + d;
    const int t0 = blockIdx.y * (T_ / KCH);
    float m[8];
#pragma unroll
    for (int j = 0; j < 8; j++) m[j] = -3.4e38f;
#pragma unroll 4
    for (int t = 0; t < T_ / KCH; t++) {
        const float4 kv = *(const float4*)(base + (size_t)(t0 + t) * D_);
        const __nv_bfloat162* p = (const __nv_bfloat162*)&kv;
#pragma unroll
        for (int j = 0; j < 4; j++) {
            m[j * 2 + 0] = fmaxf(m[j * 2 + 0], __bfloat162float(p[j].x));
            m[j * 2 + 1] = fmaxf(m[j * 2 + 1], __bfloat162float(p[j].y));
        }
    }
#pragma unroll
    for (int j = 0; j < 8; j++)
        g_cmax_part[(col0 + j) * KCH + blockIdx.y] = m[j];
}

__global__ void __launch_bounds__(256) kmax_final_kernel() {
    const int col = blockIdx.x * 256 + threadIdx.x;
    const float4* p = (const float4*)(g_cmax_part + col * KCH);
    float m = -3.4e38f;
#pragma unroll
    for (int i = 0; i < KCH / 4; i++) {
        const float4 v = p[i];
        m = fmaxf(m, fmaxf(fmaxf(v.x, v.y), fmaxf(v.z, v.w)));
    }
    g_cmax[col] = m;
}

// ---------------- att partial via HMMA: U[d][l]=sum_t E[t][d]*V[t][l] --------
__global__ void __launch_bounds__(256) att_part_kernel(const float* __restrict__ mask) {
    __shared__ __align__(16) char Eb[32 * EP];
    __shared__ __align__(16) char Vb[32 * EP];
    __shared__ float Ms[128];
    __shared__ float Sred[8][128];
    const int bh = blockIdx.x, sp = blockIdx.y;
    const int b = bh >> 3, h = bh & 7;
    const int tid = threadIdx.x, lane = tid & 31, wid = tid >> 5;
    const int wd = wid & 3, wl = wid >> 2;
    if (tid < 128) Ms[tid] = g_cmax[b * 1024 + h * 128 + tid];
    __syncthreads();

    float acc[2][8][4];
#pragma unroll
    for (int i = 0; i < 2; i++)
#pragma unroll
        for (int j = 0; j < 8; j++)
#pragma unroll
            for (int q = 0; q < 4; q++) acc[i][j][q] = 0.f;
    float ssum[4] = {0.f, 0.f, 0.f, 0.f};

    const uint32_t Ebase = smem_u32(Eb), Vbase = smem_u32(Vb);
    const size_t gbase = ((size_t)b * T_) * D_ + h * 128;
    const int tstart = sp * (T_ / NSPLIT);
    const int dc = (tid & 31) * 4;
    const float m0v = Ms[dc], m1v = Ms[dc + 1], m2v = Ms[dc + 2], m3v = Ms[dc + 3];

    for (int t0 = tstart; t0 < tstart + T_ / NSPLIT; t0 += 32) {
#pragma unroll
        for (int it = 0; it < 2; it++) {
            const int idx = it * 256 + tid;
            const int tr = idx >> 4, ch = idx & 15;
            cp16(Vbase + tr * EP + ch * 16,
                 g_vb + gbase + (size_t)(t0 + tr) * D_ + ch * 8);
        }
        CP_COMMIT();
        int myvalid = 0;
#pragma unroll
        for (int s = 0; s < 4; s++) {
            const int tr = (tid >> 5) + s * 8;
            const float mk = mask[b * T_ + t0 + tr];
            uint2 pe = {0u, 0u};
            if (mk != 0.f) {
                myvalid = 1;
                const uint2 kp = *(const uint2*)(g_kb + gbase + (size_t)(t0 + tr) * D_ + dc);
                const __nv_bfloat162 k01 = *(const __nv_bfloat162*)&kp.x;
                const __nv_bfloat162 k23 = *(const __nv_bfloat162*)&kp.y;
                const float e0 = __expf(__bfloat162float(k01.x) - m0v);
                const float e1 = __expf(__bfloat162float(k01.y) - m1v);
                const float e2 = __expf(__bfloat162float(k23.x) - m2v);
                const float e3 = __expf(__bfloat162float(k23.y) - m3v);
                ssum[0] += e0; ssum[1] += e1; ssum[2] += e2; ssum[3] += e3;
                pe.x = pack_bf16(e0, e1);
                pe.y = pack_bf16(e2, e3);
            }
            *(uint2*)(Eb + tr * EP + dc * 2) = pe;
        }
        CP_WAIT(0);
        const int anyvalid = __syncthreads_or(myvalid);
        if (anyvalid) {
#pragma unroll
            for (int ks = 0; ks < 2; ks++) {
                uint32_t a[2][4], bf[4][4];
#pragma unroll
                for (int mi = 0; mi < 2; mi++) {
                    const uint32_t ao = (uint32_t)((ks * 16 + ((lane & 16) ? 8 : 0)
                                       + (lane & 7)) * EP
                                       + (wd * 32 + mi * 16) * 2
                                       + ((lane & 8) ? 16 : 0));
                    ldsm_x4t(a[mi], Ebase + ao);
                }
#pragma unroll
                for (int nb = 0; nb < 4; nb++) {
                    const uint32_t bo = (uint32_t)((ks * 16 + ((lane & 8) ? 8 : 0)
                                       + (lane & 7)) * EP
                                       + (wl * 64 + nb * 16) * 2
                                       + ((lane & 16) ? 16 : 0));
                    ldsm_x4t(bf[nb], Vbase + bo);
                }
#pragma unroll
                for (int mi = 0; mi < 2; mi++)
#pragma unroll
                    for (int nb = 0; nb < 4; nb++)
#pragma unroll
                        for (int ns = 0; ns < 2; ns++)
                            mma16816(acc[mi][nb * 2 + ns], a[mi], &bf[nb][ns * 2]);
            }
        }
        __syncthreads();
    }

    const size_t obase = ((size_t)sp * 32 + bh) * 16384;
#pragma unroll
    for (int mi = 0; mi < 2; mi++) {
        const int d0 = wd * 32 + mi * 16 + (lane >> 2);
#pragma unroll
        for (int ni = 0; ni < 8; ni++) {
            const int l0 = wl * 64 + ni * 8 + (lane & 3) * 2;
            *(float2*)(g_attp + obase + (size_t)d0 * 128 + l0) =
                make_float2(acc[mi][ni][0], acc[mi][ni][1]);
            *(float2*)(g_attp + obase + (size_t)(d0 + 8) * 128 + l0) =
                make_float2(acc[mi][ni][2], acc[mi][ni][3]);
        }
    }
#pragma unroll
    for (int j = 0; j < 4; j++) Sred[wid][dc + j] = ssum[j];
    __syncthreads();
    if (tid < 128) {
        float s = 0.f;
#pragma unroll
        for (int r = 0; r < 8; r++) s += Sred[r][tid];
        g_Sp[(size_t)sp * 4096 + bh * 128 + tid] = s;
    }
}

// ---------------- att reduce: sum partials, normalize, emit bf16 -------------
// grid (32, 8): block handles 2048 elems (16 d-rows) of one bh.
__global__ void __launch_bounds__(256) att_reduce_kernel() {
    __shared__ float Ss[16];
    const int bh = blockIdx.x, ch = blockIdx.y;
    const int tid = threadIdx.x;
    if (tid < 16) {
        const int d = ch * 16 + tid;
        float s = 0.f;
#pragma unroll
        for (int p = 0; p < NSPLIT; p++) s += g_Sp[(size_t)p * 4096 + bh * 128 + d];
        Ss[tid] = 1.0f / s;
    }
    __syncthreads();
    const int e0 = ch * 2048;
#pragma unroll
    for (int q = 0; q < 8; q++) {
        const int e = e0 + q * 256 + tid;
        float s = 0.f;
#pragma unroll
        for (int p = 0; p < NSPLIT; p++) s += g_attp[((size_t)p * 32 + bh) * 16384 + e];
        g_attb[(size_t)bh * 16384 + e] =
            __float2bfloat16_rn(s * Ss[(e >> 7) - ch * 16]);
    }
}

// ---------------- y = q_sm @ att via HMMA, out = x + y -----------------------
#define YG_SMEM (2 * 128 * EP + 256)
__global__ void __launch_bounds__(256) ygemm_kernel(const float* __restrict__ x,
                                                    float* __restrict__ out) {
    extern __shared__ char ydsm[];
    const uint32_t qs = (smem_u32(ydsm) + 15) & ~15u;
    const uint32_t as = qs + 128 * EP;
    const int bh = blockIdx.y, mt = blockIdx.x;
    const int b = bh >> 3, h = bh & 7;
    const int tid = threadIdx.x, lane = tid & 31, wid = tid >> 5;
    const int wm = wid & 3, wl = wid >> 2;

    const size_t qgbase = ((size_t)b * T_ + mt * 128) * D_ + h * 128;
    const size_t agbase = (size_t)bh * 16384;
#pragma unroll
    for (int p = 0; p < 8; p++) {
        const int idx = p * 256 + tid;
        const int r = idx >> 4, c8 = idx & 15;
        cp16(qs + r * EP + c8 * 16, g_qb + qgbase + (size_t)r * 1024 + c8 * 8);
        cp16(as + r * EP + c8 * 16, g_attb + agbase + (size_t)r * 128 + c8 * 8);
    }
    CP_COMMIT();
    CP_WAIT(0);
    __syncthreads();

    float acc[2][8][4];
#pragma unroll
    for (int i = 0; i < 2; i++)
#pragma unroll
        for (int j = 0; j < 8; j++)
#pragma unroll
            for (int q = 0; q < 4; q++) acc[i][j][q] = 0.f;

#pragma unroll
    for (int ks = 0; ks < 8; ks++) {
        uint32_t a[2][4], bf[4][4];
#pragma unroll
        for (int mi = 0; mi < 2; mi++) {
            const uint32_t ao = (uint32_t)((wm * 32 + mi * 16 + (lane & 15)) * EP
                               + ks * 32 + ((lane & 16) ? 16 : 0));
            ldsm_x4(a[mi], qs + ao);
        }
#pragma unroll
        for (int nb = 0; nb < 4; nb++) {
            const uint32_t bo = (uint32_t)((ks * 16 + ((lane & 8) ? 8 : 0)
                               + (lane & 7)) * EP
                               + (wl * 64 + nb * 16) * 2
                               + ((lane & 16) ? 16 : 0));
            ldsm_x4t(bf[nb], as + bo);
        }
#pragma unroll
        for (int mi = 0; mi < 2; mi++)
#pragma unroll
            for (int nb = 0; nb < 4; nb++)
#pragma unroll
                for (int ns = 0; ns < 2; ns++)
                    mma16816(acc[mi][nb * 2 + ns], a[mi], &bf[nb][ns * 2]);
    }

#pragma unroll
    for (int mi = 0; mi < 2; mi++) {
        const size_t row0 = (size_t)b * T_ + mt * 128 + wm * 32 + mi * 16 + (lane >> 2);
        const size_t row1 = row0 + 8;
#pragma unroll
        for (int ni = 0; ni < 8; ni++) {
            const int c = h * 128 + wl * 64 + ni * 8 + (lane & 3) * 2;
            const float2 x0 = *(const float2*)(x + row0 * 1024 + c);
            const float2 x1 = *(const float2*)(x + row1 * 1024 + c);
            float2 o0, o1;
            o0.x = acc[mi][ni][0] + x0.x; o0.y = acc[mi][ni][1] + x0.y;
            o1.x = acc[mi][ni][2] + x1.x; o1.y = acc[mi][ni][3] + x1.y;
            *(float2*)(out + row0 * 1024 + c) = o0;
            *(float2*)(out + row1 * 1024 + c) = o1;
        }
    }
}

// ---------------- launcher ---------------------------------------------------
extern "C" void kernel_launch(void* const* d_in, const int* in_sizes, int n_in,
                              void* d_out, int out_size) {
    const float* x     = (const float*)d_in[0];
    const float* mask  = (const float*)d_in[1];
    const float* Wq    = (const float*)d_in[2];
    const float* bq    = (const float*)d_in[3];
    const float* Wk    = (const float*)d_in[4];
    const float* bk    = (const float*)d_in[5];
    const float* Wv    = (const float*)d_in[6];
    const float* bv    = (const float*)d_in[7];
    const float* gamma = (const float*)d_in[8];
    const float* beta  = (const float*)d_in[9];
    float* out = (float*)d_out;

    static int smem_set = 0;
    if (!smem_set) {
        cudaFuncSetAttribute(qkv_mma, cudaFuncAttributeMaxDynamicSharedMemorySize,
                             QK_SMEM);
        cudaFuncSetAttribute(ygemm_kernel,
                             cudaFuncAttributeMaxDynamicSharedMemorySize, YG_SMEM);
        smem_set = 1;
    }

    ln_kernel<<<NTOK, 256>>>(x, gamma, beta);
    wsplit_kernel<<<dim3(32, 32, 3), 256>>>(Wq, Wk, Wv);

    qkv_mma<<<dim3(4, 128, 3), 256, QK_SMEM>>>(bq, bk, bv, mask);

    kmax_part_kernel<<<dim3(2, KCH), 256>>>();
    kmax_final_kernel<<<16, 256>>>();

    att_part_kernel<<<dim3(32, NSPLIT), 256>>>(mask);
    att_reduce_kernel<<<dim3(32, 8), 256>>>();

    ygemm_kernel<<<dim3(32, 32), 256, YG_SMEM>>>(x, out);
}